// round 1
// baseline (speedup 1.0000x reference)
#include <cuda_runtime.h>
#include <cuda_fp16.h>
#include <mma.h>

using namespace nvcuda;

#define HEADS 8
#define DH    64
#define NMEM  4
#define DIM   512
#define BATCH 16
#define NPIX  1024            // 32*32
#define NTOK  (BATCH*NPIX)    // 16384
#define KV    1028            // 4 mem + 1024 tokens
#define KVP   1088            // padded to 17*64
#define QKV3  1536
#define HID   512
#define ZBH   (BATCH*HEADS)   // 128

// ---------------- scratch (static device allocations) ----------------
__device__ float  g_rnorm[NTOK];
__device__ __align__(16) __half g_xn  [(size_t)NTOK*DIM];
__device__ __align__(16) __half g_wqkv[(size_t)QKV3*DIM];
__device__ __align__(16) __half g_wout[(size_t)DIM*HID];
__device__ __align__(16) __half g_q   [(size_t)ZBH*NPIX*DH];
__device__ __align__(16) __half g_k   [(size_t)ZBH*KVP*DH];
__device__ __align__(16) __half g_vt  [(size_t)ZBH*DH*KVP];   // V transposed [z][d][j]
__device__ __align__(16) float  g_s   [(size_t)ZBH*NPIX*KVP];
__device__ __align__(16) __half g_p   [(size_t)ZBH*NPIX*KVP];
__device__ __align__(16) __half g_att [(size_t)NTOK*HID];

// ---------------- small prep kernels ----------------
__global__ void cvt_wqkv_kernel(const float* __restrict__ w) {
    int i = blockIdx.x * 256 + threadIdx.x;
    g_wqkv[i] = __float2half(w[i]);
}
__global__ void cvt_wout_kernel(const float* __restrict__ w) {
    int i = blockIdx.x * 256 + threadIdx.x;
    g_wout[i] = __float2half(w[i]);
}

__global__ void norm_kernel(const float* __restrict__ x) {
    int t = blockIdx.x * 256 + threadIdx.x;     // token id
    int b = t >> 10, p = t & 1023;
    const float* xp = x + (size_t)b * DIM * NPIX + p;
    float s = 0.f;
#pragma unroll 8
    for (int c = 0; c < DIM; c++) {
        float v = xp[(size_t)c * NPIX];
        s += v * v;
    }
    float nrm = sqrtf(s);
    g_rnorm[t] = 22.62741699796952f / fmaxf(nrm, 1e-12f);   // sqrt(512)/max(||x||,eps)
}

// transpose x [b][c][p] -> xn [token][c] fp16, with rnorm and (gamma+1)
__global__ void norm_apply_kernel(const float* __restrict__ x, const float* __restrict__ gamma) {
    __shared__ float tile[32][33];
    int b  = blockIdx.z;
    int c0 = blockIdx.x * 32, p0 = blockIdx.y * 32;
    int tx = threadIdx.x, ty = threadIdx.y;
    const float* xb = x + (size_t)b * DIM * NPIX;
#pragma unroll
    for (int i = 0; i < 4; i++)
        tile[ty + i * 8][tx] = xb[(size_t)(c0 + ty + i * 8) * NPIX + p0 + tx];
    __syncthreads();
#pragma unroll
    for (int i = 0; i < 4; i++) {
        int p = p0 + ty + i * 8;
        int c = c0 + tx;
        int tok = b * NPIX + p;
        float v = tile[tx][ty + i * 8] * g_rnorm[tok] * (gamma[c] + 1.0f);
        g_xn[(size_t)tok * DIM + c] = __float2half(v);
    }
}

// fill mem-KV rows 0..3 and zero-pad rows 1028..1087 of K / cols of Vt
__global__ void init_kv_kernel(const float* __restrict__ mem_kv) {
    int z = blockIdx.x;              // b*8+h
    int h = z & 7;
    __half* kz  = g_k  + (size_t)z * KVP * DH;
    __half* vtz = g_vt + (size_t)z * DH * KVP;
    for (int idx = threadIdx.x; idx < NMEM * DH; idx += blockDim.x) {
        int j = idx >> 6, d = idx & 63;
        float kv = mem_kv[(0 * HEADS + h) * NMEM * DH + j * DH + d];
        float vv = mem_kv[(1 * HEADS + h) * NMEM * DH + j * DH + d];
        kz [(size_t)j * DH + d]  = __float2half(kv);
        vtz[(size_t)d * KVP + j] = __float2half(vv);
    }
    for (int idx = threadIdx.x; idx < (KVP - KV) * DH; idx += blockDim.x) {
        int j = KV + idx / DH, d = idx % DH;
        kz [(size_t)j * DH + d]  = __float2half(0.f);
        vtz[(size_t)d * KVP + j] = __float2half(0.f);
    }
}

// ---------------- generic WMMA GEMM: C[m][n] = sum_k A[m][k]*B[n][k] ----------------
// BM=128 BN=64 BK=32, 8 warps (4x2), warp tile 32x32 (2x2 wmma frags)
#define SLD 48   // smem row stride (halfs), 96B -> uint4 aligned

// EP: 0 = qkv scatter, 1 = S write, 2 = att write, 3 = final out (transposed)
template<int EP>
__global__ void gemm_kernel(float* __restrict__ Cout) {
    __shared__ __align__(16) unsigned char smem_raw[128 * 72 * 4];   // 36864B (>= 18432B for A+B)
    __half* As = (__half*)smem_raw;                     // [128][SLD]
    __half* Bs = (__half*)(smem_raw + 128 * SLD * 2);   // [64][SLD]
    float*  Cs = (float*)smem_raw;                      // [128][72]

    constexpr int K = (EP == 0) ? DIM : (EP == 1) ? DH : (EP == 2) ? KVP : HID;
    const __half* A; const __half* B;
    size_t sA = 0, sB = 0;
    if (EP == 0)      { A = g_xn;  B = g_wqkv; }
    else if (EP == 1) { A = g_q;   B = g_k;  sA = (size_t)NPIX * DH;  sB = (size_t)KVP * DH; }
    else if (EP == 2) { A = g_p;   B = g_vt; sA = (size_t)NPIX * KVP; sB = (size_t)DH * KVP; }
    else              { A = g_att; B = g_wout; }

    int z  = blockIdx.z;
    const __half* Ab = A + (size_t)z * sA;
    const __half* Bb = B + (size_t)z * sB;
    int bm  = blockIdx.y * 128;
    int bn  = blockIdx.x * 64;
    int tid = threadIdx.x;
    int wid = tid >> 5;
    int wm  = (wid >> 1) * 32;
    int wn  = (wid & 1) * 32;

    wmma::fragment<wmma::accumulator, 16, 16, 16, float> fc[2][2];
#pragma unroll
    for (int i = 0; i < 2; i++)
#pragma unroll
        for (int j = 0; j < 2; j++)
            wmma::fill_fragment(fc[i][j], 0.0f);

    for (int k0 = 0; k0 < K; k0 += 32) {
        // A tile: 128x32 halfs = 512 uint4, 2 per thread
#pragma unroll
        for (int i = 0; i < 2; i++) {
            int v = tid + i * 256;
            int row = v >> 2, cv = v & 3;
            *(uint4*)(&As[row * SLD + cv * 8]) =
                *(const uint4*)(&Ab[(size_t)(bm + row) * K + k0 + cv * 8]);
        }
        // B tile: 64x32 halfs = 256 uint4, 1 per thread
        {
            int row = tid >> 2, cv = tid & 3;
            *(uint4*)(&Bs[row * SLD + cv * 8]) =
                *(const uint4*)(&Bb[(size_t)(bn + row) * K + k0 + cv * 8]);
        }
        __syncthreads();
#pragma unroll
        for (int kk = 0; kk < 32; kk += 16) {
            wmma::fragment<wmma::matrix_a, 16, 16, 16, __half, wmma::row_major> fa[2];
            wmma::fragment<wmma::matrix_b, 16, 16, 16, __half, wmma::col_major> fb[2];
            wmma::load_matrix_sync(fa[0], &As[(wm + 0)  * SLD + kk], SLD);
            wmma::load_matrix_sync(fa[1], &As[(wm + 16) * SLD + kk], SLD);
            wmma::load_matrix_sync(fb[0], &Bs[(wn + 0)  * SLD + kk], SLD);
            wmma::load_matrix_sync(fb[1], &Bs[(wn + 16) * SLD + kk], SLD);
#pragma unroll
            for (int i = 0; i < 2; i++)
#pragma unroll
                for (int j = 0; j < 2; j++)
                    wmma::mma_sync(fc[i][j], fa[i], fb[j], fc[i][j]);
        }
        __syncthreads();
    }

    // stage accumulators to smem, then scatter with the epilogue mapping
#pragma unroll
    for (int i = 0; i < 2; i++)
#pragma unroll
        for (int j = 0; j < 2; j++)
            wmma::store_matrix_sync(&Cs[(wm + i * 16) * 72 + wn + j * 16], fc[i][j], 72,
                                    wmma::mem_row_major);
    __syncthreads();

    for (int idx = tid; idx < 128 * 64; idx += 256) {
        int r = idx >> 6, c = idx & 63;
        float v = Cs[r * 72 + c];
        int m = bm + r, n = bn + c;
        if (EP == 0) {
            int b = m >> 10, p = m & 1023;
            if (n < 512) {
                int h = n >> 6, d = n & 63;
                g_q[(((size_t)(b * HEADS + h)) * NPIX + p) * DH + d] = __float2half(v * 0.125f);
            } else if (n < 1024) {
                int c2 = n - 512; int h = c2 >> 6, d = c2 & 63;
                g_k[((size_t)(b * HEADS + h) * KVP + NMEM + p) * DH + d] = __float2half(v);
            } else {
                int c2 = n - 1024; int h = c2 >> 6, d = c2 & 63;
                g_vt[((size_t)(b * HEADS + h) * DH + d) * KVP + NMEM + p] = __float2half(v);
            }
        } else if (EP == 1) {
            g_s[(size_t)z * NPIX * KVP + (size_t)m * KVP + n] = v;
        } else if (EP == 2) {
            int b = z >> 3, h = z & 7;
            g_att[((size_t)(b * NPIX + m)) * HID + h * DH + n] = __float2half(v);
        } else {
            int b = m >> 10, p = m & 1023;
            Cout[(size_t)b * DIM * NPIX + (size_t)n * NPIX + p] = v;
        }
    }
}

// ---------------- softmax (rows of S, masked to 1028 cols) ----------------
__global__ void softmax_kernel() {
    int row = blockIdx.x;                   // z*1024 + i, 131072 rows
    size_t off = (size_t)row * KVP;
    const float* srow = g_s + off;
    __half* prow = g_p + off;
    __shared__ float sbuf[KVP];
    __shared__ float red[4];
    int tid = threadIdx.x;                  // 128 threads

    float mx = -1e30f;
    for (int j = tid; j < KV; j += 128) {
        float v = srow[j];
        sbuf[j] = v;
        mx = fmaxf(mx, v);
    }
#pragma unroll
    for (int o = 16; o > 0; o >>= 1) mx = fmaxf(mx, __shfl_xor_sync(0xFFFFFFFF, mx, o));
    if ((tid & 31) == 0) red[tid >> 5] = mx;
    __syncthreads();
    mx = fmaxf(fmaxf(red[0], red[1]), fmaxf(red[2], red[3]));
    __syncthreads();

    float sum = 0.f;
    for (int j = tid; j < KV; j += 128) {
        float e = __expf(sbuf[j] - mx);
        sbuf[j] = e;
        sum += e;
    }
#pragma unroll
    for (int o = 16; o > 0; o >>= 1) sum += __shfl_xor_sync(0xFFFFFFFF, sum, o);
    if ((tid & 31) == 0) red[tid >> 5] = sum;
    __syncthreads();
    sum = red[0] + red[1] + red[2] + red[3];
    float inv = 1.0f / sum;

    for (int j = tid; j < KVP; j += 128)
        prow[j] = (j < KV) ? __float2half(sbuf[j] * inv) : __float2half(0.f);
}

// ---------------- launcher ----------------
extern "C" void kernel_launch(void* const* d_in, const int* in_sizes, int n_in,
                              void* d_out, int out_size) {
    const float* x      = (const float*)d_in[0];
    const float* gamma  = (const float*)d_in[1];
    const float* mem_kv = (const float*)d_in[2];
    const float* w_qkv  = (const float*)d_in[3];
    const float* w_out  = (const float*)d_in[4];
    float* out = (float*)d_out;

    cvt_wqkv_kernel<<<(QKV3 * DIM) / 256, 256>>>(w_qkv);
    cvt_wout_kernel<<<(DIM * HID) / 256, 256>>>(w_out);
    norm_kernel<<<NTOK / 256, 256>>>(x);
    norm_apply_kernel<<<dim3(DIM / 32, NPIX / 32, BATCH), dim3(32, 8)>>>(x, gamma);
    init_kv_kernel<<<ZBH, 256>>>(mem_kv);

    // GEMM1: qkv projection [16384 x 1536 x 512] -> scatter to q/k/vt
    gemm_kernel<0><<<dim3(QKV3 / 64, NTOK / 128, 1), 256>>>(nullptr);
    // GEMM2: S = Q K^T  per (b,h): [1024 x 1088 x 64]
    gemm_kernel<1><<<dim3(KVP / 64, NPIX / 128, ZBH), 256>>>(nullptr);
    // softmax rows
    softmax_kernel<<<ZBH * NPIX, 128>>>();
    // GEMM3: O = P V  per (b,h): [1024 x 64 x 1088]
    gemm_kernel<2><<<dim3(1, NPIX / 128, ZBH), 256>>>(nullptr);
    // GEMM4: out projection [16384 x 512 x 512] -> transposed fp32 write
    gemm_kernel<3><<<dim3(HID / 64, NTOK / 128, 1), 256>>>(out);
}

// round 2
// speedup vs baseline: 2.1862x; 2.1862x over previous
#include <cuda_runtime.h>
#include <cuda_fp16.h>
#include <mma.h>
#include <cstdint>

using namespace nvcuda;

#define HEADS 8
#define DH    64
#define NMEM  4
#define DIM   512
#define BATCH 16
#define NPIX  1024            // 32*32
#define NTOK  (BATCH*NPIX)    // 16384
#define KV    1028            // 4 mem + 1024 tokens
#define KVP   1088            // padded to 17*64
#define QKV3  1536
#define HID   512
#define ZBH   (BATCH*HEADS)   // 128

// ---------------- scratch (static device allocations) ----------------
__device__ float  g_rnorm[NTOK];
__device__ __align__(16) __half g_xn  [(size_t)NTOK*DIM];
__device__ __align__(16) __half g_wqkv[(size_t)QKV3*DIM];
__device__ __align__(16) __half g_wout[(size_t)DIM*HID];
__device__ __align__(16) __half g_q   [(size_t)ZBH*NPIX*DH];
__device__ __align__(16) __half g_k   [(size_t)ZBH*KVP*DH];
__device__ __align__(16) __half g_v   [(size_t)ZBH*KVP*DH];   // [z][j][d]
__device__ __align__(16) __half g_att [(size_t)NTOK*HID];

// ---------------- small prep kernels ----------------
__global__ void cvt_wqkv_kernel(const float* __restrict__ w) {
    int i = blockIdx.x * 256 + threadIdx.x;
    g_wqkv[i] = __float2half(w[i]);
}
__global__ void cvt_wout_kernel(const float* __restrict__ w) {
    int i = blockIdx.x * 256 + threadIdx.x;
    g_wout[i] = __float2half(w[i]);
}

__global__ void norm_kernel(const float* __restrict__ x) {
    int t = blockIdx.x * 256 + threadIdx.x;     // token id
    int b = t >> 10, p = t & 1023;
    const float* xp = x + (size_t)b * DIM * NPIX + p;
    float s = 0.f;
#pragma unroll 8
    for (int c = 0; c < DIM; c++) {
        float v = xp[(size_t)c * NPIX];
        s += v * v;
    }
    float nrm = sqrtf(s);
    g_rnorm[t] = 22.62741699796952f / fmaxf(nrm, 1e-12f);   // sqrt(512)/max(||x||,eps)
}

// transpose x [b][c][p] -> xn [token][c] fp16, with rnorm and (gamma+1)
__global__ void norm_apply_kernel(const float* __restrict__ x, const float* __restrict__ gamma) {
    __shared__ float tile[32][33];
    int b  = blockIdx.z;
    int c0 = blockIdx.x * 32, p0 = blockIdx.y * 32;
    int tx = threadIdx.x, ty = threadIdx.y;
    const float* xb = x + (size_t)b * DIM * NPIX;
#pragma unroll
    for (int i = 0; i < 4; i++)
        tile[ty + i * 8][tx] = xb[(size_t)(c0 + ty + i * 8) * NPIX + p0 + tx];
    __syncthreads();
#pragma unroll
    for (int i = 0; i < 4; i++) {
        int p = p0 + ty + i * 8;
        int c = c0 + tx;
        int tok = b * NPIX + p;
        float v = tile[tx][ty + i * 8] * g_rnorm[tok] * (gamma[c] + 1.0f);
        g_xn[(size_t)tok * DIM + c] = __float2half(v);
    }
}

// fill mem-KV rows 0..3 and zero-pad rows 1028..1087 of K / V
__global__ void init_kv_kernel(const float* __restrict__ mem_kv) {
    int z = blockIdx.x;              // b*8+h
    int h = z & 7;
    __half* kz = g_k + (size_t)z * KVP * DH;
    __half* vz = g_v + (size_t)z * KVP * DH;
    for (int idx = threadIdx.x; idx < NMEM * DH; idx += blockDim.x) {
        int j = idx >> 6, d = idx & 63;
        float kv = mem_kv[(0 * HEADS + h) * NMEM * DH + j * DH + d];
        float vv = mem_kv[(1 * HEADS + h) * NMEM * DH + j * DH + d];
        kz[(size_t)j * DH + d] = __float2half(kv);
        vz[(size_t)j * DH + d] = __float2half(vv);
    }
    for (int idx = threadIdx.x; idx < (KVP - KV) * DH; idx += blockDim.x) {
        int j = KV + idx / DH, d = idx % DH;
        kz[(size_t)j * DH + d] = __float2half(0.f);
        vz[(size_t)j * DH + d] = __float2half(0.f);
    }
}

// ---------------- generic WMMA GEMM: C[m][n] = sum_k A[m][k]*B[n][k] ----------------
#define SLD 48   // smem row stride (halfs)

// EP: 0 = qkv scatter, 3 = final out (transposed)
template<int EP>
__global__ void gemm_kernel(float* __restrict__ Cout) {
    __shared__ __align__(16) unsigned char smem_raw[128 * 72 * 4];
    __half* As = (__half*)smem_raw;                     // [128][SLD]
    __half* Bs = (__half*)(smem_raw + 128 * SLD * 2);   // [64][SLD]
    float*  Cs = (float*)smem_raw;                      // [128][72]

    constexpr int K = (EP == 0) ? DIM : HID;
    const __half* A = (EP == 0) ? g_xn  : g_att;
    const __half* B = (EP == 0) ? g_wqkv : g_wout;

    int bm  = blockIdx.y * 128;
    int bn  = blockIdx.x * 64;
    int tid = threadIdx.x;
    int wid = tid >> 5;
    int wm  = (wid >> 1) * 32;
    int wn  = (wid & 1) * 32;

    wmma::fragment<wmma::accumulator, 16, 16, 16, float> fc[2][2];
#pragma unroll
    for (int i = 0; i < 2; i++)
#pragma unroll
        for (int j = 0; j < 2; j++)
            wmma::fill_fragment(fc[i][j], 0.0f);

    for (int k0 = 0; k0 < K; k0 += 32) {
#pragma unroll
        for (int i = 0; i < 2; i++) {
            int v = tid + i * 256;
            int row = v >> 2, cv = v & 3;
            *(uint4*)(&As[row * SLD + cv * 8]) =
                *(const uint4*)(&A[(size_t)(bm + row) * K + k0 + cv * 8]);
        }
        {
            int row = tid >> 2, cv = tid & 3;
            *(uint4*)(&Bs[row * SLD + cv * 8]) =
                *(const uint4*)(&B[(size_t)(bn + row) * K + k0 + cv * 8]);
        }
        __syncthreads();
#pragma unroll
        for (int kk = 0; kk < 32; kk += 16) {
            wmma::fragment<wmma::matrix_a, 16, 16, 16, __half, wmma::row_major> fa[2];
            wmma::fragment<wmma::matrix_b, 16, 16, 16, __half, wmma::col_major> fb[2];
            wmma::load_matrix_sync(fa[0], &As[(wm + 0)  * SLD + kk], SLD);
            wmma::load_matrix_sync(fa[1], &As[(wm + 16) * SLD + kk], SLD);
            wmma::load_matrix_sync(fb[0], &Bs[(wn + 0)  * SLD + kk], SLD);
            wmma::load_matrix_sync(fb[1], &Bs[(wn + 16) * SLD + kk], SLD);
#pragma unroll
            for (int i = 0; i < 2; i++)
#pragma unroll
                for (int j = 0; j < 2; j++)
                    wmma::mma_sync(fc[i][j], fa[i], fb[j], fc[i][j]);
        }
        __syncthreads();
    }

#pragma unroll
    for (int i = 0; i < 2; i++)
#pragma unroll
        for (int j = 0; j < 2; j++)
            wmma::store_matrix_sync(&Cs[(wm + i * 16) * 72 + wn + j * 16], fc[i][j], 72,
                                    wmma::mem_row_major);
    __syncthreads();

    for (int idx = tid; idx < 128 * 64; idx += 256) {
        int r = idx >> 6, c = idx & 63;
        float v = Cs[r * 72 + c];
        int m = bm + r, n = bn + c;
        if (EP == 0) {
            int b = m >> 10, p = m & 1023;
            if (n < 512) {
                int h = n >> 6, d = n & 63;
                g_q[(((size_t)(b * HEADS + h)) * NPIX + p) * DH + d] = __float2half(v * 0.125f);
            } else if (n < 1024) {
                int c2 = n - 512; int h = c2 >> 6, d = c2 & 63;
                g_k[((size_t)(b * HEADS + h) * KVP + NMEM + p) * DH + d] = __float2half(v);
            } else {
                int c2 = n - 1024; int h = c2 >> 6, d = c2 & 63;
                g_v[((size_t)(b * HEADS + h) * KVP + NMEM + p) * DH + d] = __float2half(v);
            }
        } else {
            int b = m >> 10, p = m & 1023;
            Cout[(size_t)b * DIM * NPIX + (size_t)n * NPIX + p] = v;
        }
    }
}

// ---------------- fused flash attention ----------------
__device__ __forceinline__ uint32_t smem_u32(const void* p) {
    return (uint32_t)__cvta_generic_to_shared(p);
}
__device__ __forceinline__ void ldsm_x4(uint32_t& r0, uint32_t& r1, uint32_t& r2, uint32_t& r3,
                                        uint32_t a) {
    asm volatile("ldmatrix.sync.aligned.m8n8.x4.shared.b16 {%0,%1,%2,%3},[%4];"
                 : "=r"(r0), "=r"(r1), "=r"(r2), "=r"(r3) : "r"(a));
}
__device__ __forceinline__ void ldsm_x4_t(uint32_t& r0, uint32_t& r1, uint32_t& r2, uint32_t& r3,
                                          uint32_t a) {
    asm volatile("ldmatrix.sync.aligned.m8n8.x4.trans.shared.b16 {%0,%1,%2,%3},[%4];"
                 : "=r"(r0), "=r"(r1), "=r"(r2), "=r"(r3) : "r"(a));
}
__device__ __forceinline__ void mma16816(float* c, const uint32_t* a, const uint32_t* b) {
    asm volatile(
        "mma.sync.aligned.m16n8k16.row.col.f32.f16.f16.f32 "
        "{%0,%1,%2,%3},{%4,%5,%6,%7},{%8,%9},{%0,%1,%2,%3};"
        : "+f"(c[0]), "+f"(c[1]), "+f"(c[2]), "+f"(c[3])
        : "r"(a[0]), "r"(a[1]), "r"(a[2]), "r"(a[3]), "r"(b[0]), "r"(b[1]));
}
__device__ __forceinline__ uint32_t packh2(float a, float b) {
    __half2 h = __floats2half2_rn(a, b);
    return *(uint32_t*)&h;
}

#define FS 72   // smem row stride in halves (144B: 16B aligned, ldmatrix conflict-free)

__global__ void __launch_bounds__(256) flash_kernel() {
    __shared__ __align__(16) __half sQ[128 * FS];
    __shared__ __align__(16) __half sK[64 * FS];
    __shared__ __align__(16) __half sV[64 * FS];

    int z   = blockIdx.y;
    int m0  = blockIdx.x * 128;
    int tid = threadIdx.x, wid = tid >> 5, lane = tid & 31;

    const __half* Qg = g_q + ((size_t)z * NPIX + m0) * DH;
    const __half* Kg = g_k + (size_t)z * KVP * DH;
    const __half* Vg = g_v + (size_t)z * KVP * DH;

    // load Q tile (stays resident)
    for (int i = tid; i < 128 * 8; i += 256) {
        int r = i >> 3, cv = i & 7;
        *(uint4*)&sQ[r * FS + cv * 8] = *(const uint4*)&Qg[(size_t)r * DH + cv * 8];
    }
    __syncthreads();

    // Q A-fragments, invariant across KV chunks
    uint32_t aQ[4][4];
    {
        uint32_t base = smem_u32(&sQ[(wid * 16 + (lane & 15)) * FS + (lane >> 4) * 8]);
#pragma unroll
        for (int kk = 0; kk < 4; kk++)
            ldsm_x4(aQ[kk][0], aQ[kk][1], aQ[kk][2], aQ[kk][3], base + kk * 32);
    }

    float o[8][4];
#pragma unroll
    for (int i = 0; i < 8; i++)
#pragma unroll
        for (int j = 0; j < 4; j++) o[i][j] = 0.f;
    float mrun0 = -1e30f, mrun1 = -1e30f, l0 = 0.f, l1 = 0.f;

    int rowp = ((lane >> 4) & 1) * 8 + (lane & 7);
    int colp = ((lane >> 3) & 1) * 8;
    uint32_t kb = smem_u32(sK) + (rowp * FS + colp) * 2;
    uint32_t vb = smem_u32(sV) + (((lane & 7) + ((lane >> 3) & 1) * 8) * FS
                                  + ((lane >> 4) & 1) * 8) * 2;

    for (int ch = 0; ch < 17; ch++) {
        int j0 = ch * 64;
        for (int i = tid; i < 64 * 8; i += 256) {
            int r = i >> 3, cv = i & 7;
            *(uint4*)&sK[r * FS + cv * 8] = *(const uint4*)&Kg[(size_t)(j0 + r) * DH + cv * 8];
            *(uint4*)&sV[r * FS + cv * 8] = *(const uint4*)&Vg[(size_t)(j0 + r) * DH + cv * 8];
        }
        __syncthreads();

        // S = Q K^T  (warp owns 16 rows x 64 cols)
        float s[8][4];
#pragma unroll
        for (int i = 0; i < 8; i++)
#pragma unroll
            for (int j = 0; j < 4; j++) s[i][j] = 0.f;
#pragma unroll
        for (int kk = 0; kk < 4; kk++)
#pragma unroll
            for (int jnp = 0; jnp < 4; jnp++) {
                uint32_t b[4];
                ldsm_x4(b[0], b[1], b[2], b[3], kb + (jnp * 16 * FS + kk * 16) * 2);
                mma16816(s[2 * jnp], aQ[kk], b);
                mma16816(s[2 * jnp + 1], aQ[kk], b + 2);
            }

        if (ch == 16) {   // mask padded columns j >= 1028
            int q2 = 2 * (lane & 3);
#pragma unroll
            for (int jn = 0; jn < 8; jn++) {
                int j = 1024 + jn * 8 + q2;
                if (j >= KV)     { s[jn][0] = -1e30f; s[jn][2] = -1e30f; }
                if (j + 1 >= KV) { s[jn][1] = -1e30f; s[jn][3] = -1e30f; }
            }
        }

        // online softmax
        float mc0 = -1e30f, mc1 = -1e30f;
#pragma unroll
        for (int jn = 0; jn < 8; jn++) {
            mc0 = fmaxf(mc0, fmaxf(s[jn][0], s[jn][1]));
            mc1 = fmaxf(mc1, fmaxf(s[jn][2], s[jn][3]));
        }
        mc0 = fmaxf(mc0, __shfl_xor_sync(0xFFFFFFFF, mc0, 1));
        mc0 = fmaxf(mc0, __shfl_xor_sync(0xFFFFFFFF, mc0, 2));
        mc1 = fmaxf(mc1, __shfl_xor_sync(0xFFFFFFFF, mc1, 1));
        mc1 = fmaxf(mc1, __shfl_xor_sync(0xFFFFFFFF, mc1, 2));

        float mn0 = fmaxf(mrun0, mc0), mn1 = fmaxf(mrun1, mc1);
        float al0 = __expf(mrun0 - mn0), al1 = __expf(mrun1 - mn1);
        mrun0 = mn0; mrun1 = mn1;

        float lc0 = 0.f, lc1 = 0.f;
        uint32_t aP[4][4];
#pragma unroll
        for (int jnp = 0; jnp < 4; jnp++) {
            float p00 = __expf(s[2 * jnp][0] - mn0), p01 = __expf(s[2 * jnp][1] - mn0);
            float p02 = __expf(s[2 * jnp][2] - mn1), p03 = __expf(s[2 * jnp][3] - mn1);
            float p10 = __expf(s[2 * jnp + 1][0] - mn0), p11 = __expf(s[2 * jnp + 1][1] - mn0);
            float p12 = __expf(s[2 * jnp + 1][2] - mn1), p13 = __expf(s[2 * jnp + 1][3] - mn1);
            lc0 += p00 + p01 + p10 + p11;
            lc1 += p02 + p03 + p12 + p13;
            aP[jnp][0] = packh2(p00, p01);
            aP[jnp][1] = packh2(p02, p03);
            aP[jnp][2] = packh2(p10, p11);
            aP[jnp][3] = packh2(p12, p13);
        }
        lc0 += __shfl_xor_sync(0xFFFFFFFF, lc0, 1);
        lc0 += __shfl_xor_sync(0xFFFFFFFF, lc0, 2);
        lc1 += __shfl_xor_sync(0xFFFFFFFF, lc1, 1);
        lc1 += __shfl_xor_sync(0xFFFFFFFF, lc1, 2);
        l0 = l0 * al0 + lc0;
        l1 = l1 * al1 + lc1;

#pragma unroll
        for (int dn = 0; dn < 8; dn++) {
            o[dn][0] *= al0; o[dn][1] *= al0;
            o[dn][2] *= al1; o[dn][3] *= al1;
        }

        // O += P V
#pragma unroll
        for (int kp = 0; kp < 4; kp++)
#pragma unroll
            for (int dnp = 0; dnp < 4; dnp++) {
                uint32_t b[4];
                ldsm_x4_t(b[0], b[1], b[2], b[3], vb + (kp * 16 * FS + dnp * 16) * 2);
                mma16816(o[2 * dnp], aP[kp], b);
                mma16816(o[2 * dnp + 1], aP[kp], b + 2);
            }
        __syncthreads();
    }

    // epilogue: normalize and write to g_att [token][h*64+d]
    float inv0 = 1.f / l0, inv1 = 1.f / l1;
    int b = z >> 3, h = z & 7;
    int r0 = m0 + wid * 16 + (lane >> 2);
    __half* outp = g_att + ((size_t)(b * NPIX + r0)) * HID + h * DH + 2 * (lane & 3);
#pragma unroll
    for (int dn = 0; dn < 8; dn++) {
        __half2 v0 = __floats2half2_rn(o[dn][0] * inv0, o[dn][1] * inv0);
        __half2 v1 = __floats2half2_rn(o[dn][2] * inv1, o[dn][3] * inv1);
        *(__half2*)(outp + dn * 8) = v0;
        *(__half2*)(outp + dn * 8 + (size_t)8 * HID) = v1;
    }
}

// ---------------- launcher ----------------
extern "C" void kernel_launch(void* const* d_in, const int* in_sizes, int n_in,
                              void* d_out, int out_size) {
    const float* x      = (const float*)d_in[0];
    const float* gamma  = (const float*)d_in[1];
    const float* mem_kv = (const float*)d_in[2];
    const float* w_qkv  = (const float*)d_in[3];
    const float* w_out  = (const float*)d_in[4];
    float* out = (float*)d_out;

    cvt_wqkv_kernel<<<(QKV3 * DIM) / 256, 256>>>(w_qkv);
    cvt_wout_kernel<<<(DIM * HID) / 256, 256>>>(w_out);
    norm_kernel<<<NTOK / 256, 256>>>(x);
    norm_apply_kernel<<<dim3(DIM / 32, NPIX / 32, BATCH), dim3(32, 8)>>>(x, gamma);
    init_kv_kernel<<<ZBH, 256>>>(mem_kv);

    // GEMM1: qkv projection [16384 x 1536 x 512] -> scatter to q/k/v
    gemm_kernel<0><<<dim3(QKV3 / 64, NTOK / 128, 1), 256>>>(nullptr);
    // fused attention: per (z, 128-query tile)
    flash_kernel<<<dim3(NPIX / 128, ZBH), 256>>>();
    // GEMM4: out projection [16384 x 512 x 512] -> transposed fp32 write
    gemm_kernel<3><<<dim3(HID / 64, NTOK / 128, 1), 256>>>(out);
}

// round 3
// speedup vs baseline: 2.7639x; 1.2642x over previous
#include <cuda_runtime.h>
#include <cuda_fp16.h>
#include <mma.h>
#include <cstdint>

using namespace nvcuda;

#define HEADS 8
#define DH    64
#define NMEM  4
#define DIM   512
#define BATCH 16
#define NPIX  1024            // 32*32
#define NTOK  (BATCH*NPIX)    // 16384
#define KV    1028            // 4 mem + 1024 tokens
#define KVP   1088            // padded to 17*64
#define QKV3  1536
#define HID   512
#define ZBH   (BATCH*HEADS)   // 128

// ---------------- scratch (static device allocations) ----------------
__device__ float  g_rnorm[NTOK];
__device__ __align__(16) __half g_xn  [(size_t)NTOK*DIM];
__device__ __align__(16) __half g_wqkv[(size_t)QKV3*DIM];
__device__ __align__(16) __half g_wout[(size_t)DIM*HID];
__device__ __align__(16) __half g_q   [(size_t)ZBH*NPIX*DH];
__device__ __align__(16) __half g_k   [(size_t)ZBH*KVP*DH];
__device__ __align__(16) __half g_v   [(size_t)ZBH*KVP*DH];   // [z][j][d]
__device__ __align__(16) __half g_att [(size_t)NTOK*HID];

// ---------------- async copy helpers ----------------
__device__ __forceinline__ uint32_t smem_u32(const void* p) {
    return (uint32_t)__cvta_generic_to_shared(p);
}
__device__ __forceinline__ void cp16(void* dst, const void* src) {
    asm volatile("cp.async.cg.shared.global [%0],[%1],16;"
                 :: "r"(smem_u32(dst)), "l"(src));
}
#define CP_COMMIT() asm volatile("cp.async.commit_group;")
#define CP_WAIT(n)  asm volatile("cp.async.wait_group %0;" :: "n"(n))

// ---------------- small prep kernels ----------------
__global__ void cvt_wqkv_kernel(const float* __restrict__ w) {
    int i = blockIdx.x * 256 + threadIdx.x;
    g_wqkv[i] = __float2half(w[i]);
}
__global__ void cvt_wout_kernel(const float* __restrict__ w) {
    int i = blockIdx.x * 256 + threadIdx.x;
    g_wout[i] = __float2half(w[i]);
}

__global__ void norm_kernel(const float* __restrict__ x) {
    int t = blockIdx.x * 256 + threadIdx.x;     // token id
    int b = t >> 10, p = t & 1023;
    const float* xp = x + (size_t)b * DIM * NPIX + p;
    float s = 0.f;
#pragma unroll 8
    for (int c = 0; c < DIM; c++) {
        float v = xp[(size_t)c * NPIX];
        s += v * v;
    }
    float nrm = sqrtf(s);
    g_rnorm[t] = 22.62741699796952f / fmaxf(nrm, 1e-12f);   // sqrt(512)/max(||x||,eps)
}

// transpose x [b][c][p] -> xn [token][c] fp16, with rnorm and (gamma+1)
__global__ void norm_apply_kernel(const float* __restrict__ x, const float* __restrict__ gamma) {
    __shared__ float tile[32][33];
    int b  = blockIdx.z;
    int c0 = blockIdx.x * 32, p0 = blockIdx.y * 32;
    int tx = threadIdx.x, ty = threadIdx.y;
    const float* xb = x + (size_t)b * DIM * NPIX;
#pragma unroll
    for (int i = 0; i < 4; i++)
        tile[ty + i * 8][tx] = xb[(size_t)(c0 + ty + i * 8) * NPIX + p0 + tx];
    __syncthreads();
#pragma unroll
    for (int i = 0; i < 4; i++) {
        int p = p0 + ty + i * 8;
        int c = c0 + tx;
        int tok = b * NPIX + p;
        float v = tile[tx][ty + i * 8] * g_rnorm[tok] * (gamma[c] + 1.0f);
        g_xn[(size_t)tok * DIM + c] = __float2half(v);
    }
}

// fill mem-KV rows 0..3 and zero-pad rows 1028..1087 of K / V
__global__ void init_kv_kernel(const float* __restrict__ mem_kv) {
    int z = blockIdx.x;              // b*8+h
    int h = z & 7;
    __half* kz = g_k + (size_t)z * KVP * DH;
    __half* vz = g_v + (size_t)z * KVP * DH;
    for (int idx = threadIdx.x; idx < NMEM * DH; idx += blockDim.x) {
        int j = idx >> 6, d = idx & 63;
        float kv = mem_kv[(0 * HEADS + h) * NMEM * DH + j * DH + d];
        float vv = mem_kv[(1 * HEADS + h) * NMEM * DH + j * DH + d];
        kz[(size_t)j * DH + d] = __float2half(kv);
        vz[(size_t)j * DH + d] = __float2half(vv);
    }
    for (int idx = threadIdx.x; idx < (KVP - KV) * DH; idx += blockDim.x) {
        int j = KV + idx / DH, d = idx % DH;
        kz[(size_t)j * DH + d] = __float2half(0.f);
        vz[(size_t)j * DH + d] = __float2half(0.f);
    }
}

// ------- pipelined WMMA GEMM: C[m][n] = sum_k A[m][k]*B[n][k], K=512 -------
// BM=128, BN=128, BK=32, double-buffered cp.async. 8 warps, warp tile 32x64.
#define SLD 40   // smem row stride in halfs (80B = odd multiple of 16B -> conflict-free)

// EP: 0 = qkv scatter, 3 = final out (transposed, coalesced along p)
template<int EP>
__global__ void __launch_bounds__(256) gemm_kernel(float* __restrict__ Cout) {
    __shared__ __align__(16) unsigned char gsm[2 * 2 * 128 * SLD * 2];   // 40960 B
    __half* As[2] = { (__half*)gsm,                 (__half*)(gsm + 128 * SLD * 2) };
    __half* Bs[2] = { (__half*)(gsm + 2*128*SLD*2), (__half*)(gsm + 3*128*SLD*2) };

    const __half* A = (EP == 0) ? g_xn  : g_att;
    const __half* B = (EP == 0) ? g_wqkv : g_wout;

    int bm  = blockIdx.y * 128;
    int bn  = blockIdx.x * 128;
    int tid = threadIdx.x;
    int wid = tid >> 5, lane = tid & 31;
    int wm  = (wid >> 1) * 32;
    int wn  = (wid & 1) * 64;

    wmma::fragment<wmma::accumulator, 16, 16, 16, float> fc[2][4];
#pragma unroll
    for (int i = 0; i < 2; i++)
#pragma unroll
        for (int j = 0; j < 4; j++)
            wmma::fill_fragment(fc[i][j], 0.0f);

    const int NK = 512 / 32;   // 16
    int lr = tid >> 2, lcv = tid & 3;

#pragma unroll 1
    for (int ks = 0; ks < NK; ks++) {
        if (ks == 0) {
#pragma unroll
            for (int i = 0; i < 2; i++) {
                int r = lr + i * 64;
                cp16(&As[0][r * SLD + lcv * 8], &A[(size_t)(bm + r) * 512 + lcv * 8]);
                cp16(&Bs[0][r * SLD + lcv * 8], &B[(size_t)(bn + r) * 512 + lcv * 8]);
            }
            CP_COMMIT();
        }
        if (ks + 1 < NK) {
            int k0 = (ks + 1) * 32, nb = (ks + 1) & 1;
#pragma unroll
            for (int i = 0; i < 2; i++) {
                int r = lr + i * 64;
                cp16(&As[nb][r * SLD + lcv * 8], &A[(size_t)(bm + r) * 512 + k0 + lcv * 8]);
                cp16(&Bs[nb][r * SLD + lcv * 8], &B[(size_t)(bn + r) * 512 + k0 + lcv * 8]);
            }
            CP_COMMIT();
            CP_WAIT(1);
        } else {
            CP_WAIT(0);
        }
        __syncthreads();

        int buf = ks & 1;
#pragma unroll
        for (int kk = 0; kk < 32; kk += 16) {
            wmma::fragment<wmma::matrix_a, 16, 16, 16, __half, wmma::row_major> fa[2];
            wmma::fragment<wmma::matrix_b, 16, 16, 16, __half, wmma::col_major> fb[4];
            wmma::load_matrix_sync(fa[0], &As[buf][(wm + 0)  * SLD + kk], SLD);
            wmma::load_matrix_sync(fa[1], &As[buf][(wm + 16) * SLD + kk], SLD);
#pragma unroll
            for (int j = 0; j < 4; j++)
                wmma::load_matrix_sync(fb[j], &Bs[buf][(wn + j * 16) * SLD + kk], SLD);
#pragma unroll
            for (int i = 0; i < 2; i++)
#pragma unroll
                for (int j = 0; j < 4; j++)
                    wmma::mma_sync(fc[i][j], fa[i], fb[j], fc[i][j]);
        }
        __syncthreads();
    }

    // per-warp epilogue: stage each 16x16 frag to warp-private smem, then scatter
    float* Wc = (float*)gsm + wid * 256;
#pragma unroll
    for (int i = 0; i < 2; i++)
#pragma unroll
        for (int j = 0; j < 4; j++) {
            wmma::store_matrix_sync(Wc, fc[i][j], 16, wmma::mem_row_major);
            __syncwarp();
            int m0 = bm + wm + i * 16, n0 = bn + wn + j * 16;
#pragma unroll
            for (int t = 0; t < 8; t++) {
                int e = t * 32 + lane;
                if (EP == 0) {
                    int r = e >> 4, c = e & 15;
                    float v = Wc[r * 16 + c];
                    int m = m0 + r, n = n0 + c;
                    int b = m >> 10, p = m & 1023;
                    if (n < 512) {
                        int h = n >> 6, d = n & 63;
                        g_q[(((size_t)(b * HEADS + h)) * NPIX + p) * DH + d] =
                            __float2half(v * 0.125f);
                    } else if (n < 1024) {
                        int c2 = n - 512; int h = c2 >> 6, d = c2 & 63;
                        g_k[((size_t)(b * HEADS + h) * KVP + NMEM + p) * DH + d] = __float2half(v);
                    } else {
                        int c2 = n - 1024; int h = c2 >> 6, d = c2 & 63;
                        g_v[((size_t)(b * HEADS + h) * KVP + NMEM + p) * DH + d] = __float2half(v);
                    }
                } else {
                    int r = e & 15, c = e >> 4;   // lanes -> rows (p) for coalesced fp32 store
                    float v = Wc[r * 16 + c];
                    int m = m0 + r, n = n0 + c;
                    int b = m >> 10, p = m & 1023;
                    Cout[(size_t)b * DIM * NPIX + (size_t)n * NPIX + p] = v;
                }
            }
            __syncwarp();
        }
}

// ---------------- fused flash attention ----------------
__device__ __forceinline__ void ldsm_x4(uint32_t& r0, uint32_t& r1, uint32_t& r2, uint32_t& r3,
                                        uint32_t a) {
    asm volatile("ldmatrix.sync.aligned.m8n8.x4.shared.b16 {%0,%1,%2,%3},[%4];"
                 : "=r"(r0), "=r"(r1), "=r"(r2), "=r"(r3) : "r"(a));
}
__device__ __forceinline__ void ldsm_x4_t(uint32_t& r0, uint32_t& r1, uint32_t& r2, uint32_t& r3,
                                          uint32_t a) {
    asm volatile("ldmatrix.sync.aligned.m8n8.x4.trans.shared.b16 {%0,%1,%2,%3},[%4];"
                 : "=r"(r0), "=r"(r1), "=r"(r2), "=r"(r3) : "r"(a));
}
__device__ __forceinline__ void mma16816(float* c, const uint32_t* a, const uint32_t* b) {
    asm volatile(
        "mma.sync.aligned.m16n8k16.row.col.f32.f16.f16.f32 "
        "{%0,%1,%2,%3},{%4,%5,%6,%7},{%8,%9},{%0,%1,%2,%3};"
        : "+f"(c[0]), "+f"(c[1]), "+f"(c[2]), "+f"(c[3])
        : "r"(a[0]), "r"(a[1]), "r"(a[2]), "r"(a[3]), "r"(b[0]), "r"(b[1]));
}
__device__ __forceinline__ uint32_t packh2(float a, float b) {
    __half2 h = __floats2half2_rn(a, b);
    return *(uint32_t*)&h;
}

#define FS 72   // smem row stride in halves (144B = odd multiple of 16B)

__global__ void __launch_bounds__(256) flash_kernel() {
    // union: Q tile first (9216 halfs), then double-buffered K/V (4 * 64*FS)
    __shared__ __align__(16) __half fsm[4 * 64 * FS];   // 36864 B
    __half* sQ = fsm;

    int z   = blockIdx.y;
    int m0  = blockIdx.x * 128;
    int tid = threadIdx.x, wid = tid >> 5, lane = tid & 31;

    const __half* Qg = g_q + ((size_t)z * NPIX + m0) * DH;
    const __half* Kg = g_k + (size_t)z * KVP * DH;
    const __half* Vg = g_v + (size_t)z * KVP * DH;

    // load Q tile, build invariant A-fragments, then smem is recycled for K/V
    for (int i = tid; i < 128 * 8; i += 256) {
        int r = i >> 3, cv = i & 7;
        *(uint4*)&sQ[r * FS + cv * 8] = *(const uint4*)&Qg[(size_t)r * DH + cv * 8];
    }
    __syncthreads();

    uint32_t aQ[4][4];
    {
        uint32_t base = smem_u32(&sQ[(wid * 16 + (lane & 15)) * FS + (lane >> 4) * 8]);
#pragma unroll
        for (int kk = 0; kk < 4; kk++)
            ldsm_x4(aQ[kk][0], aQ[kk][1], aQ[kk][2], aQ[kk][3], base + kk * 32);
    }
    __syncthreads();

    float o[8][4];
#pragma unroll
    for (int i = 0; i < 8; i++)
#pragma unroll
        for (int j = 0; j < 4; j++) o[i][j] = 0.f;
    float mrun0 = -1e30f, mrun1 = -1e30f, l0 = 0.f, l1 = 0.f;

    int rowp = ((lane >> 4) & 1) * 8 + (lane & 7);
    int colp = ((lane >> 3) & 1) * 8;
    uint32_t koff = (uint32_t)(rowp * FS + colp) * 2;
    uint32_t voff = (uint32_t)((((lane & 7) + ((lane >> 3) & 1) * 8) * FS
                                + ((lane >> 4) & 1) * 8) * 2);
    uint32_t kbase[2] = { smem_u32(fsm) + koff,
                          smem_u32(fsm + 128 * FS) + koff };
    uint32_t vbase[2] = { smem_u32(fsm + 64 * FS) + voff,
                          smem_u32(fsm + 192 * FS) + voff };
    __half* sKb[2] = { fsm,            fsm + 128 * FS };
    __half* sVb[2] = { fsm + 64 * FS,  fsm + 192 * FS };

    int ldr = tid >> 2, ldc = (tid & 3) * 2;   // 64 rows, 4 vec-pairs

#pragma unroll 1
    for (int ch = 0; ch < 17; ch++) {
        if (ch == 0) {
            cp16(&sKb[0][ldr * FS + ldc * 8],       &Kg[(size_t)ldr * DH + ldc * 8]);
            cp16(&sKb[0][ldr * FS + (ldc + 1) * 8], &Kg[(size_t)ldr * DH + (ldc + 1) * 8]);
            cp16(&sVb[0][ldr * FS + ldc * 8],       &Vg[(size_t)ldr * DH + ldc * 8]);
            cp16(&sVb[0][ldr * FS + (ldc + 1) * 8], &Vg[(size_t)ldr * DH + (ldc + 1) * 8]);
            CP_COMMIT();
        }
        if (ch + 1 < 17) {
            int j0 = (ch + 1) * 64, nb = (ch + 1) & 1;
            cp16(&sKb[nb][ldr * FS + ldc * 8],       &Kg[(size_t)(j0 + ldr) * DH + ldc * 8]);
            cp16(&sKb[nb][ldr * FS + (ldc + 1) * 8], &Kg[(size_t)(j0 + ldr) * DH + (ldc + 1) * 8]);
            cp16(&sVb[nb][ldr * FS + ldc * 8],       &Vg[(size_t)(j0 + ldr) * DH + ldc * 8]);
            cp16(&sVb[nb][ldr * FS + (ldc + 1) * 8], &Vg[(size_t)(j0 + ldr) * DH + (ldc + 1) * 8]);
            CP_COMMIT();
            CP_WAIT(1);
        } else {
            CP_WAIT(0);
        }
        __syncthreads();

        int buf = ch & 1;
        uint32_t kb = kbase[buf], vb = vbase[buf];

        // S = Q K^T  (warp owns 16 rows x 64 cols)
        float s[8][4];
#pragma unroll
        for (int i = 0; i < 8; i++)
#pragma unroll
            for (int j = 0; j < 4; j++) s[i][j] = 0.f;
#pragma unroll
        for (int kk = 0; kk < 4; kk++)
#pragma unroll
            for (int jnp = 0; jnp < 4; jnp++) {
                uint32_t b[4];
                ldsm_x4(b[0], b[1], b[2], b[3], kb + (jnp * 16 * FS + kk * 16) * 2);
                mma16816(s[2 * jnp], aQ[kk], b);
                mma16816(s[2 * jnp + 1], aQ[kk], b + 2);
            }

        if (ch == 16) {   // mask padded columns j >= 1028
            int q2 = 2 * (lane & 3);
#pragma unroll
            for (int jn = 0; jn < 8; jn++) {
                int j = 1024 + jn * 8 + q2;
                if (j >= KV)     { s[jn][0] = -1e30f; s[jn][2] = -1e30f; }
                if (j + 1 >= KV) { s[jn][1] = -1e30f; s[jn][3] = -1e30f; }
            }
        }

        // online softmax
        float mc0 = -1e30f, mc1 = -1e30f;
#pragma unroll
        for (int jn = 0; jn < 8; jn++) {
            mc0 = fmaxf(mc0, fmaxf(s[jn][0], s[jn][1]));
            mc1 = fmaxf(mc1, fmaxf(s[jn][2], s[jn][3]));
        }
        mc0 = fmaxf(mc0, __shfl_xor_sync(0xFFFFFFFF, mc0, 1));
        mc0 = fmaxf(mc0, __shfl_xor_sync(0xFFFFFFFF, mc0, 2));
        mc1 = fmaxf(mc1, __shfl_xor_sync(0xFFFFFFFF, mc1, 1));
        mc1 = fmaxf(mc1, __shfl_xor_sync(0xFFFFFFFF, mc1, 2));

        float mn0 = fmaxf(mrun0, mc0), mn1 = fmaxf(mrun1, mc1);
        float al0 = __expf(mrun0 - mn0), al1 = __expf(mrun1 - mn1);
        mrun0 = mn0; mrun1 = mn1;

        float lc0 = 0.f, lc1 = 0.f;
        uint32_t aP[4][4];
#pragma unroll
        for (int jnp = 0; jnp < 4; jnp++) {
            float p00 = __expf(s[2 * jnp][0] - mn0), p01 = __expf(s[2 * jnp][1] - mn0);
            float p02 = __expf(s[2 * jnp][2] - mn1), p03 = __expf(s[2 * jnp][3] - mn1);
            float p10 = __expf(s[2 * jnp + 1][0] - mn0), p11 = __expf(s[2 * jnp + 1][1] - mn0);
            float p12 = __expf(s[2 * jnp + 1][2] - mn1), p13 = __expf(s[2 * jnp + 1][3] - mn1);
            lc0 += p00 + p01 + p10 + p11;
            lc1 += p02 + p03 + p12 + p13;
            aP[jnp][0] = packh2(p00, p01);
            aP[jnp][1] = packh2(p02, p03);
            aP[jnp][2] = packh2(p10, p11);
            aP[jnp][3] = packh2(p12, p13);
        }
        lc0 += __shfl_xor_sync(0xFFFFFFFF, lc0, 1);
        lc0 += __shfl_xor_sync(0xFFFFFFFF, lc0, 2);
        lc1 += __shfl_xor_sync(0xFFFFFFFF, lc1, 1);
        lc1 += __shfl_xor_sync(0xFFFFFFFF, lc1, 2);
        l0 = l0 * al0 + lc0;
        l1 = l1 * al1 + lc1;

#pragma unroll
        for (int dn = 0; dn < 8; dn++) {
            o[dn][0] *= al0; o[dn][1] *= al0;
            o[dn][2] *= al1; o[dn][3] *= al1;
        }

        // O += P V
#pragma unroll
        for (int kp = 0; kp < 4; kp++)
#pragma unroll
            for (int dnp = 0; dnp < 4; dnp++) {
                uint32_t b[4];
                ldsm_x4_t(b[0], b[1], b[2], b[3], vb + (kp * 16 * FS + dnp * 16) * 2);
                mma16816(o[2 * dnp], aP[kp], b);
                mma16816(o[2 * dnp + 1], aP[kp], b + 2);
            }
        __syncthreads();
    }

    // epilogue: normalize and write to g_att [token][h*64+d]
    float inv0 = 1.f / l0, inv1 = 1.f / l1;
    int b = z >> 3, h = z & 7;
    int r0 = m0 + wid * 16 + (lane >> 2);
    __half* outp = g_att + ((size_t)(b * NPIX + r0)) * HID + h * DH + 2 * (lane & 3);
#pragma unroll
    for (int dn = 0; dn < 8; dn++) {
        __half2 v0 = __floats2half2_rn(o[dn][0] * inv0, o[dn][1] * inv0);
        __half2 v1 = __floats2half2_rn(o[dn][2] * inv1, o[dn][3] * inv1);
        *(__half2*)(outp + dn * 8) = v0;
        *(__half2*)(outp + dn * 8 + (size_t)8 * HID) = v1;
    }
}

// ---------------- launcher ----------------
extern "C" void kernel_launch(void* const* d_in, const int* in_sizes, int n_in,
                              void* d_out, int out_size) {
    const float* x      = (const float*)d_in[0];
    const float* gamma  = (const float*)d_in[1];
    const float* mem_kv = (const float*)d_in[2];
    const float* w_qkv  = (const float*)d_in[3];
    const float* w_out  = (const float*)d_in[4];
    float* out = (float*)d_out;

    cvt_wqkv_kernel<<<(QKV3 * DIM) / 256, 256>>>(w_qkv);
    cvt_wout_kernel<<<(DIM * HID) / 256, 256>>>(w_out);
    norm_kernel<<<NTOK / 256, 256>>>(x);
    norm_apply_kernel<<<dim3(DIM / 32, NPIX / 32, BATCH), dim3(32, 8)>>>(x, gamma);
    init_kv_kernel<<<ZBH, 256>>>(mem_kv);

    // GEMM1: qkv projection [16384 x 1536 x 512] -> scatter to q/k/v
    gemm_kernel<0><<<dim3(QKV3 / 128, NTOK / 128, 1), 256>>>(nullptr);
    // fused attention: per (z, 128-query tile)
    flash_kernel<<<dim3(NPIX / 128, ZBH), 256>>>();
    // GEMM4: out projection [16384 x 512 x 512] -> transposed fp32 write
    gemm_kernel<3><<<dim3(HID / 128, NTOK / 128, 1), 256>>>(out);
}

// round 6
// speedup vs baseline: 2.8083x; 1.0161x over previous
#include <cuda_runtime.h>
#include <cuda_fp16.h>
#include <mma.h>
#include <cstdint>

using namespace nvcuda;

#define HEADS 8
#define DH    64
#define NMEM  4
#define DIM   512
#define BATCH 16
#define NPIX  1024            // 32*32
#define NTOK  (BATCH*NPIX)    // 16384
#define KV    1028            // 4 mem + 1024 tokens
#define KVP   1088            // padded to 17*64
#define QKV3  1536
#define HID   512
#define ZBH   (BATCH*HEADS)   // 128

// ---------------- scratch (static device allocations) ----------------
__device__ float  g_rnorm[NTOK];
__device__ __align__(16) __half g_xn  [(size_t)NTOK*DIM];
__device__ __align__(16) __half g_wqkv[(size_t)QKV3*DIM];
__device__ __align__(16) __half g_wout[(size_t)DIM*HID];
__device__ __align__(16) __half g_q   [(size_t)ZBH*NPIX*DH];
__device__ __align__(16) __half g_k   [(size_t)ZBH*KVP*DH];
__device__ __align__(16) __half g_v   [(size_t)ZBH*KVP*DH];   // [z][j][d]
__device__ __align__(16) __half g_att [(size_t)NTOK*HID];

// ---------------- async copy helpers ----------------
__device__ __forceinline__ uint32_t smem_u32(const void* p) {
    return (uint32_t)__cvta_generic_to_shared(p);
}
__device__ __forceinline__ void cp16(void* dst, const void* src) {
    asm volatile("cp.async.cg.shared.global [%0],[%1],16;"
                 :: "r"(smem_u32(dst)), "l"(src));
}
#define CP_COMMIT() asm volatile("cp.async.commit_group;")
#define CP_WAIT(n)  asm volatile("cp.async.wait_group %0;" :: "n"(n))

// ---------------- small prep kernels ----------------
__global__ void cvt_w_kernel(const float* __restrict__ wq, const float* __restrict__ wo) {
    int i = blockIdx.x * 256 + threadIdx.x;
    if (i < QKV3 * DIM) g_wqkv[i] = __float2half(wq[i]);
    else {
        int j = i - QKV3 * DIM;
        g_wout[j] = __float2half(wo[j]);
    }
}

__global__ void norm_kernel(const float* __restrict__ x) {
    int t = blockIdx.x * 256 + threadIdx.x;     // token id
    int b = t >> 10, p = t & 1023;
    const float* xp = x + (size_t)b * DIM * NPIX + p;
    float s = 0.f;
#pragma unroll 8
    for (int c = 0; c < DIM; c++) {
        float v = xp[(size_t)c * NPIX];
        s += v * v;
    }
    float nrm = sqrtf(s);
    g_rnorm[t] = 22.62741699796952f / fmaxf(nrm, 1e-12f);   // sqrt(512)/max(||x||,eps)
}

// transpose x [b][c][p] -> xn [token][c] fp16, with rnorm and (gamma+1)
__global__ void norm_apply_kernel(const float* __restrict__ x, const float* __restrict__ gamma) {
    __shared__ float tile[32][33];
    int b  = blockIdx.z;
    int c0 = blockIdx.x * 32, p0 = blockIdx.y * 32;
    int tx = threadIdx.x, ty = threadIdx.y;
    const float* xb = x + (size_t)b * DIM * NPIX;
#pragma unroll
    for (int i = 0; i < 4; i++)
        tile[ty + i * 8][tx] = xb[(size_t)(c0 + ty + i * 8) * NPIX + p0 + tx];
    __syncthreads();
#pragma unroll
    for (int i = 0; i < 4; i++) {
        int p = p0 + ty + i * 8;
        int c = c0 + tx;
        int tok = b * NPIX + p;
        float v = tile[tx][ty + i * 8] * g_rnorm[tok] * (gamma[c] + 1.0f);
        g_xn[(size_t)tok * DIM + c] = __float2half(v);
    }
}

// fill mem-KV rows 0..3 and zero-pad rows 1028..1087 of K / V
__global__ void init_kv_kernel(const float* __restrict__ mem_kv) {
    int z = blockIdx.x;              // b*8+h
    int h = z & 7;
    __half* kz = g_k + (size_t)z * KVP * DH;
    __half* vz = g_v + (size_t)z * KVP * DH;
    for (int idx = threadIdx.x; idx < NMEM * DH; idx += blockDim.x) {
        int j = idx >> 6, d = idx & 63;
        kz[(size_t)j * DH + d] = __float2half(mem_kv[(0 * HEADS + h) * NMEM * DH + j * DH + d]);
        vz[(size_t)j * DH + d] = __float2half(mem_kv[(1 * HEADS + h) * NMEM * DH + j * DH + d]);
    }
    for (int idx = threadIdx.x; idx < (KVP - KV) * DH; idx += blockDim.x) {
        int j = KV + idx / DH, d = idx % DH;
        kz[(size_t)j * DH + d] = __float2half(0.f);
        vz[(size_t)j * DH + d] = __float2half(0.f);
    }
}

// ------- pipelined WMMA GEMM: C[m][n] = sum_k A[m][k]*B[n][k], K=512 -------
// BM=128, BN=128, BK=32. 3-stage cp.async ring, ONE barrier per slab.
#define SLD 40                        // smem row stride in halfs (80B)
#define GSTG (128 * SLD * 2)          // 10240 B per A or B per stage
#define GSMEM (3 * 2 * GSTG)          // 61440 B

// EP: 0 = qkv scatter, 3 = final out (transposed, coalesced along p)
template<int EP>
__global__ void __launch_bounds__(256) gemm_kernel(float* __restrict__ Cout) {
    extern __shared__ __align__(16) unsigned char dyn[];
    __half* As[3] = { (__half*)(dyn),
                      (__half*)(dyn + 2 * GSTG),
                      (__half*)(dyn + 4 * GSTG) };
    __half* Bs[3] = { (__half*)(dyn + GSTG),
                      (__half*)(dyn + 3 * GSTG),
                      (__half*)(dyn + 5 * GSTG) };

    const __half* A = (EP == 0) ? g_xn  : g_att;
    const __half* B = (EP == 0) ? g_wqkv : g_wout;

    int bm  = blockIdx.y * 128;
    int bn  = blockIdx.x * 128;
    int tid = threadIdx.x;
    int wid = tid >> 5, lane = tid & 31;
    int wm  = (wid >> 1) * 32;
    int wn  = (wid & 1) * 64;

    wmma::fragment<wmma::accumulator, 16, 16, 16, float> fc[2][4];
#pragma unroll
    for (int i = 0; i < 2; i++)
#pragma unroll
        for (int j = 0; j < 4; j++)
            wmma::fill_fragment(fc[i][j], 0.0f);

    const int NK = 512 / 32;   // 16 slabs
    int lr = tid >> 2, lcv = tid & 3;
    const __half* Ar0 = A + (size_t)(bm + lr) * 512 + lcv * 8;
    const __half* Ar1 = A + (size_t)(bm + lr + 64) * 512 + lcv * 8;
    const __half* Br0 = B + (size_t)(bn + lr) * 512 + lcv * 8;
    const __half* Br1 = B + (size_t)(bn + lr + 64) * 512 + lcv * 8;

    // preload slabs 0 and 1
#pragma unroll
    for (int s = 0; s < 2; s++) {
        int k0 = s * 32;
        cp16(&As[s][lr * SLD + lcv * 8],        Ar0 + k0);
        cp16(&As[s][(lr + 64) * SLD + lcv * 8], Ar1 + k0);
        cp16(&Bs[s][lr * SLD + lcv * 8],        Br0 + k0);
        cp16(&Bs[s][(lr + 64) * SLD + lcv * 8], Br1 + k0);
        CP_COMMIT();
    }

#pragma unroll 1
    for (int ks = 0; ks < NK; ks++) {
        if (ks < NK - 1) CP_WAIT(1); else CP_WAIT(0);
        __syncthreads();
        // refill the stage consumed at ks-1 (safe: everyone passed the sync)
        if (ks + 2 < NK) {
            int st = (ks + 2) % 3, k0 = (ks + 2) * 32;
            cp16(&As[st][lr * SLD + lcv * 8],        Ar0 + k0);
            cp16(&As[st][(lr + 64) * SLD + lcv * 8], Ar1 + k0);
            cp16(&Bs[st][lr * SLD + lcv * 8],        Br0 + k0);
            cp16(&Bs[st][(lr + 64) * SLD + lcv * 8], Br1 + k0);
            CP_COMMIT();
        }
        int buf = ks % 3;
#pragma unroll
        for (int kk = 0; kk < 32; kk += 16) {
            wmma::fragment<wmma::matrix_a, 16, 16, 16, __half, wmma::row_major> fa[2];
            wmma::fragment<wmma::matrix_b, 16, 16, 16, __half, wmma::col_major> fb[4];
            wmma::load_matrix_sync(fa[0], &As[buf][(wm + 0)  * SLD + kk], SLD);
            wmma::load_matrix_sync(fa[1], &As[buf][(wm + 16) * SLD + kk], SLD);
#pragma unroll
            for (int j = 0; j < 4; j++)
                wmma::load_matrix_sync(fb[j], &Bs[buf][(wn + j * 16) * SLD + kk], SLD);
#pragma unroll
            for (int i = 0; i < 2; i++)
#pragma unroll
                for (int j = 0; j < 4; j++)
                    wmma::mma_sync(fc[i][j], fa[i], fb[j], fc[i][j]);
        }
    }
    __syncthreads();   // protect smem reuse in epilogue

    // per-warp epilogue: stage each 16x16 frag to warp-private smem, then scatter
    float* Wc = (float*)dyn + wid * 256;
#pragma unroll
    for (int i = 0; i < 2; i++)
#pragma unroll
        for (int j = 0; j < 4; j++) {
            wmma::store_matrix_sync(Wc, fc[i][j], 16, wmma::mem_row_major);
            __syncwarp();
            int m0 = bm + wm + i * 16, n0 = bn + wn + j * 16;
#pragma unroll
            for (int t = 0; t < 8; t++) {
                int e = t * 32 + lane;
                if (EP == 0) {
                    int r = e >> 4, c = e & 15;
                    float v = Wc[r * 16 + c];
                    int m = m0 + r, n = n0 + c;
                    int b = m >> 10, p = m & 1023;
                    if (n < 512) {
                        int h = n >> 6, d = n & 63;
                        g_q[(((size_t)(b * HEADS + h)) * NPIX + p) * DH + d] =
                            __float2half(v * 0.125f);
                    } else if (n < 1024) {
                        int c2 = n - 512; int h = c2 >> 6, d = c2 & 63;
                        g_k[((size_t)(b * HEADS + h) * KVP + NMEM + p) * DH + d] = __float2half(v);
                    } else {
                        int c2 = n - 1024; int h = c2 >> 6, d = c2 & 63;
                        g_v[((size_t)(b * HEADS + h) * KVP + NMEM + p) * DH + d] = __float2half(v);
                    }
                } else {
                    int r = e & 15, c = e >> 4;   // lanes -> rows (p) for coalesced fp32 store
                    float v = Wc[r * 16 + c];
                    int m = m0 + r, n = n0 + c;
                    int b = m >> 10, p = m & 1023;
                    Cout[(size_t)b * DIM * NPIX + (size_t)n * NPIX + p] = v;
                }
            }
            __syncwarp();
        }
}

// ---------------- fused flash attention ----------------
__device__ __forceinline__ void ldsm_x4(uint32_t& r0, uint32_t& r1, uint32_t& r2, uint32_t& r3,
                                        uint32_t a) {
    asm volatile("ldmatrix.sync.aligned.m8n8.x4.shared.b16 {%0,%1,%2,%3},[%4];"
                 : "=r"(r0), "=r"(r1), "=r"(r2), "=r"(r3) : "r"(a));
}
__device__ __forceinline__ void ldsm_x4_t(uint32_t& r0, uint32_t& r1, uint32_t& r2, uint32_t& r3,
                                          uint32_t a) {
    asm volatile("ldmatrix.sync.aligned.m8n8.x4.trans.shared.b16 {%0,%1,%2,%3},[%4];"
                 : "=r"(r0), "=r"(r1), "=r"(r2), "=r"(r3) : "r"(a));
}
__device__ __forceinline__ void mma16816(float* c, const uint32_t* a, const uint32_t* b) {
    asm volatile(
        "mma.sync.aligned.m16n8k16.row.col.f32.f16.f16.f32 "
        "{%0,%1,%2,%3},{%4,%5,%6,%7},{%8,%9},{%0,%1,%2,%3};"
        : "+f"(c[0]), "+f"(c[1]), "+f"(c[2]), "+f"(c[3])
        : "r"(a[0]), "r"(a[1]), "r"(a[2]), "r"(a[3]), "r"(b[0]), "r"(b[1]));
}
__device__ __forceinline__ uint32_t packh2(float a, float b) {
    __half2 h = __floats2half2_rn(a, b);
    return *(uint32_t*)&h;
}

#define FS 72                          // smem row stride in halves (144B)
#define FSTG (64 * FS * 2)             // 9216 B per K or V per stage
#define FSMEM (3 * 2 * FSTG)           // 55296 B

__global__ void __launch_bounds__(256) flash_kernel() {
    extern __shared__ __align__(16) unsigned char fdyn[];
    __half* sQ = (__half*)fdyn;        // aliases the ring before prefetch starts
    __half* sKb[3] = { (__half*)(fdyn),
                       (__half*)(fdyn + 2 * FSTG),
                       (__half*)(fdyn + 4 * FSTG) };
    __half* sVb[3] = { (__half*)(fdyn + FSTG),
                       (__half*)(fdyn + 3 * FSTG),
                       (__half*)(fdyn + 5 * FSTG) };

    int z   = blockIdx.y;
    int m0  = blockIdx.x * 128;
    int tid = threadIdx.x, wid = tid >> 5, lane = tid & 31;

    const __half* Qg = g_q + ((size_t)z * NPIX + m0) * DH;
    const __half* Kg = g_k + (size_t)z * KVP * DH;
    const __half* Vg = g_v + (size_t)z * KVP * DH;

    // load Q tile, build invariant A-fragments, then smem is recycled for K/V
    for (int i = tid; i < 128 * 8; i += 256) {
        int r = i >> 3, cv = i & 7;
        *(uint4*)&sQ[r * FS + cv * 8] = *(const uint4*)&Qg[(size_t)r * DH + cv * 8];
    }
    __syncthreads();

    uint32_t aQ[4][4];
    {
        uint32_t base = smem_u32(&sQ[(wid * 16 + (lane & 15)) * FS + (lane >> 4) * 8]);
#pragma unroll
        for (int kk = 0; kk < 4; kk++)
            ldsm_x4(aQ[kk][0], aQ[kk][1], aQ[kk][2], aQ[kk][3], base + kk * 32);
    }
    __syncthreads();

    float o[8][4];
#pragma unroll
    for (int i = 0; i < 8; i++)
#pragma unroll
        for (int j = 0; j < 4; j++) o[i][j] = 0.f;
    float mrun0 = -1e30f, mrun1 = -1e30f, l0 = 0.f, l1 = 0.f;

    int rowp = ((lane >> 4) & 1) * 8 + (lane & 7);
    int colp = ((lane >> 3) & 1) * 8;
    uint32_t koff = (uint32_t)(rowp * FS + colp) * 2;
    uint32_t voff = (uint32_t)((((lane & 7) + ((lane >> 3) & 1) * 8) * FS
                                + ((lane >> 4) & 1) * 8) * 2);
    uint32_t kbase[3], vbase[3];
#pragma unroll
    for (int s = 0; s < 3; s++) {
        kbase[s] = smem_u32(sKb[s]) + koff;
        vbase[s] = smem_u32(sVb[s]) + voff;
    }

    int ldr = tid >> 2, ldc = (tid & 3) * 2;

    // preload chunks 0 and 1
#pragma unroll
    for (int s = 0; s < 2; s++) {
        int j0 = s * 64;
        cp16(&sKb[s][ldr * FS + ldc * 8],       &Kg[(size_t)(j0 + ldr) * DH + ldc * 8]);
        cp16(&sKb[s][ldr * FS + (ldc + 1) * 8], &Kg[(size_t)(j0 + ldr) * DH + (ldc + 1) * 8]);
        cp16(&sVb[s][ldr * FS + ldc * 8],       &Vg[(size_t)(j0 + ldr) * DH + ldc * 8]);
        cp16(&sVb[s][ldr * FS + (ldc + 1) * 8], &Vg[(size_t)(j0 + ldr) * DH + (ldc + 1) * 8]);
        CP_COMMIT();
    }

#pragma unroll 1
    for (int ch = 0; ch < 17; ch++) {
        if (ch < 16) CP_WAIT(1); else CP_WAIT(0);
        __syncthreads();
        if (ch + 2 < 17) {
            int st = (ch + 2) % 3, j0 = (ch + 2) * 64;
            cp16(&sKb[st][ldr * FS + ldc * 8],       &Kg[(size_t)(j0 + ldr) * DH + ldc * 8]);
            cp16(&sKb[st][ldr * FS + (ldc + 1) * 8], &Kg[(size_t)(j0 + ldr) * DH + (ldc + 1) * 8]);
            cp16(&sVb[st][ldr * FS + ldc * 8],       &Vg[(size_t)(j0 + ldr) * DH + ldc * 8]);
            cp16(&sVb[st][ldr * FS + (ldc + 1) * 8], &Vg[(size_t)(j0 + ldr) * DH + (ldc + 1) * 8]);
            CP_COMMIT();
        }

        int buf = ch % 3;
        uint32_t kb = kbase[buf], vb = vbase[buf];

        // S = Q K^T  (warp owns 16 rows x 64 cols)
        float s[8][4];
#pragma unroll
        for (int i = 0; i < 8; i++)
#pragma unroll
            for (int j = 0; j < 4; j++) s[i][j] = 0.f;
#pragma unroll
        for (int kk = 0; kk < 4; kk++)
#pragma unroll
            for (int jnp = 0; jnp < 4; jnp++) {
                uint32_t b[4];
                ldsm_x4(b[0], b[1], b[2], b[3], kb + (jnp * 16 * FS + kk * 16) * 2);
                mma16816(s[2 * jnp], aQ[kk], b);
                mma16816(s[2 * jnp + 1], aQ[kk], b + 2);
            }

        if (ch == 16) {   // mask padded columns j >= 1028
            int q2 = 2 * (lane & 3);
#pragma unroll
            for (int jn = 0; jn < 8; jn++) {
                int j = 1024 + jn * 8 + q2;
                if (j >= KV)     { s[jn][0] = -1e30f; s[jn][2] = -1e30f; }
                if (j + 1 >= KV) { s[jn][1] = -1e30f; s[jn][3] = -1e30f; }
            }
        }

        // online softmax
        float mc0 = -1e30f, mc1 = -1e30f;
#pragma unroll
        for (int jn = 0; jn < 8; jn++) {
            mc0 = fmaxf(mc0, fmaxf(s[jn][0], s[jn][1]));
            mc1 = fmaxf(mc1, fmaxf(s[jn][2], s[jn][3]));
        }
        mc0 = fmaxf(mc0, __shfl_xor_sync(0xFFFFFFFF, mc0, 1));
        mc0 = fmaxf(mc0, __shfl_xor_sync(0xFFFFFFFF, mc0, 2));
        mc1 = fmaxf(mc1, __shfl_xor_sync(0xFFFFFFFF, mc1, 1));
        mc1 = fmaxf(mc1, __shfl_xor_sync(0xFFFFFFFF, mc1, 2));

        float mn0 = fmaxf(mrun0, mc0), mn1 = fmaxf(mrun1, mc1);
        float al0 = __expf(mrun0 - mn0), al1 = __expf(mrun1 - mn1);
        mrun0 = mn0; mrun1 = mn1;

        float lc0 = 0.f, lc1 = 0.f;
        uint32_t aP[4][4];
#pragma unroll
        for (int jnp = 0; jnp < 4; jnp++) {
            float p00 = __expf(s[2 * jnp][0] - mn0), p01 = __expf(s[2 * jnp][1] - mn0);
            float p02 = __expf(s[2 * jnp][2] - mn1), p03 = __expf(s[2 * jnp][3] - mn1);
            float p10 = __expf(s[2 * jnp + 1][0] - mn0), p11 = __expf(s[2 * jnp + 1][1] - mn0);
            float p12 = __expf(s[2 * jnp + 1][2] - mn1), p13 = __expf(s[2 * jnp + 1][3] - mn1);
            lc0 += p00 + p01 + p10 + p11;
            lc1 += p02 + p03 + p12 + p13;
            aP[jnp][0] = packh2(p00, p01);
            aP[jnp][1] = packh2(p02, p03);
            aP[jnp][2] = packh2(p10, p11);
            aP[jnp][3] = packh2(p12, p13);
        }
        lc0 += __shfl_xor_sync(0xFFFFFFFF, lc0, 1);
        lc0 += __shfl_xor_sync(0xFFFFFFFF, lc0, 2);
        lc1 += __shfl_xor_sync(0xFFFFFFFF, lc1, 1);
        lc1 += __shfl_xor_sync(0xFFFFFFFF, lc1, 2);
        l0 = l0 * al0 + lc0;
        l1 = l1 * al1 + lc1;

#pragma unroll
        for (int dn = 0; dn < 8; dn++) {
            o[dn][0] *= al0; o[dn][1] *= al0;
            o[dn][2] *= al1; o[dn][3] *= al1;
        }

        // O += P V
#pragma unroll
        for (int kp = 0; kp < 4; kp++)
#pragma unroll
            for (int dnp = 0; dnp < 4; dnp++) {
                uint32_t b[4];
                ldsm_x4_t(b[0], b[1], b[2], b[3], vb + (kp * 16 * FS + dnp * 16) * 2);
                mma16816(o[2 * dnp], aP[kp], b);
                mma16816(o[2 * dnp + 1], aP[kp], b + 2);
            }
    }

    // epilogue: normalize and write to g_att [token][h*64+d]
    float inv0 = 1.f / l0, inv1 = 1.f / l1;
    int b = z >> 3, h = z & 7;
    int r0 = m0 + wid * 16 + (lane >> 2);
    __half* outp = g_att + ((size_t)(b * NPIX + r0)) * HID + h * DH + 2 * (lane & 3);
#pragma unroll
    for (int dn = 0; dn < 8; dn++) {
        __half2 v0 = __floats2half2_rn(o[dn][0] * inv0, o[dn][1] * inv0);
        __half2 v1 = __floats2half2_rn(o[dn][2] * inv1, o[dn][3] * inv1);
        *(__half2*)(outp + dn * 8) = v0;
        *(__half2*)(outp + dn * 8 + (size_t)8 * HID) = v1;
    }
}

// ---------------- launcher ----------------
extern "C" void kernel_launch(void* const* d_in, const int* in_sizes, int n_in,
                              void* d_out, int out_size) {
    const float* x      = (const float*)d_in[0];
    const float* gamma  = (const float*)d_in[1];
    const float* mem_kv = (const float*)d_in[2];
    const float* w_qkv  = (const float*)d_in[3];
    const float* w_out  = (const float*)d_in[4];
    float* out = (float*)d_out;

    static int attr_done = 0;
    cudaFuncSetAttribute(gemm_kernel<0>, cudaFuncAttributeMaxDynamicSharedMemorySize, GSMEM);
    cudaFuncSetAttribute(gemm_kernel<3>, cudaFuncAttributeMaxDynamicSharedMemorySize, GSMEM);
    cudaFuncSetAttribute(flash_kernel,   cudaFuncAttributeMaxDynamicSharedMemorySize, FSMEM);
    (void)attr_done;

    cvt_w_kernel<<<(QKV3 * DIM + DIM * HID) / 256, 256>>>(w_qkv, w_out);
    norm_kernel<<<NTOK / 256, 256>>>(x);
    norm_apply_kernel<<<dim3(DIM / 32, NPIX / 32, BATCH), dim3(32, 8)>>>(x, gamma);
    init_kv_kernel<<<ZBH, 256>>>(mem_kv);

    // GEMM1: qkv projection [16384 x 1536 x 512] -> scatter to q/k/v
    gemm_kernel<0><<<dim3(QKV3 / 128, NTOK / 128), 256, GSMEM>>>(nullptr);
    // fused flash attention: per (z, 128-query tile)
    flash_kernel<<<dim3(NPIX / 128, ZBH), 256, FSMEM>>>();
    // GEMM4: out projection [16384 x 512 x 512] -> transposed fp32 write
    gemm_kernel<3><<<dim3(HID / 128, NTOK / 128), 256, GSMEM>>>(out);
}

// round 8
// speedup vs baseline: 2.9258x; 1.0418x over previous
#include <cuda_runtime.h>
#include <cuda_fp16.h>
#include <mma.h>
#include <cstdint>

using namespace nvcuda;

#define HEADS 8
#define DH    64
#define NMEM  4
#define DIM   512
#define BATCH 16
#define NPIX  1024            // 32*32
#define NTOK  (BATCH*NPIX)    // 16384
#define KV    1028            // 4 mem + 1024 tokens
#define KVP   1088            // padded to 17*64
#define QKV3  1536
#define HID   512
#define ZBH   (BATCH*HEADS)   // 128

// Q pre-scale: (1/sqrt(64)) * log2(e), so softmax runs in the 2^x domain
#define QSCALE 0.1803368801111204f

// ---------------- scratch (static device allocations) ----------------
__device__ float  g_rnorm[NTOK];
__device__ __align__(16) __half g_xn  [(size_t)NTOK*DIM];
__device__ __align__(16) __half g_wqkv[(size_t)QKV3*DIM];
__device__ __align__(16) __half g_wout[(size_t)DIM*HID];
__device__ __align__(16) __half g_q   [(size_t)ZBH*NPIX*DH];
__device__ __align__(16) __half g_k   [(size_t)ZBH*KVP*DH];
__device__ __align__(16) __half g_v   [(size_t)ZBH*KVP*DH];   // [z][j][d]
__device__ __align__(16) __half g_att [(size_t)NTOK*HID];

// ---------------- async copy helpers ----------------
__device__ __forceinline__ uint32_t smem_u32(const void* p) {
    return (uint32_t)__cvta_generic_to_shared(p);
}
__device__ __forceinline__ void cp16(void* dst, const void* src) {
    asm volatile("cp.async.cg.shared.global [%0],[%1],16;"
                 :: "r"(smem_u32(dst)), "l"(src));
}
#define CP_COMMIT() asm volatile("cp.async.commit_group;")
#define CP_WAIT(n)  asm volatile("cp.async.wait_group %0;" :: "n"(n))

// ---------------- small prep kernels ----------------
__global__ void cvt_w_kernel(const float* __restrict__ wq, const float* __restrict__ wo) {
    int i = blockIdx.x * 256 + threadIdx.x;
    if (i < QKV3 * DIM) g_wqkv[i] = __float2half(wq[i]);
    else {
        int j = i - QKV3 * DIM;
        g_wout[j] = __float2half(wo[j]);
    }
}

__global__ void norm_kernel(const float* __restrict__ x) {
    int t = blockIdx.x * 256 + threadIdx.x;     // token id
    int b = t >> 10, p = t & 1023;
    const float* xp = x + (size_t)b * DIM * NPIX + p;
    float s = 0.f;
#pragma unroll 8
    for (int c = 0; c < DIM; c++) {
        float v = xp[(size_t)c * NPIX];
        s += v * v;
    }
    float nrm = sqrtf(s);
    g_rnorm[t] = 22.62741699796952f / fmaxf(nrm, 1e-12f);   // sqrt(512)/max(||x||,eps)
}

// transpose x [b][c][p] -> xn [token][c] fp16, with rnorm and (gamma+1)
__global__ void norm_apply_kernel(const float* __restrict__ x, const float* __restrict__ gamma) {
    __shared__ float tile[32][33];
    int b  = blockIdx.z;
    int c0 = blockIdx.x * 32, p0 = blockIdx.y * 32;
    int tx = threadIdx.x, ty = threadIdx.y;
    const float* xb = x + (size_t)b * DIM * NPIX;
#pragma unroll
    for (int i = 0; i < 4; i++)
        tile[ty + i * 8][tx] = xb[(size_t)(c0 + ty + i * 8) * NPIX + p0 + tx];
    __syncthreads();
#pragma unroll
    for (int i = 0; i < 4; i++) {
        int p = p0 + ty + i * 8;
        int c = c0 + tx;
        int tok = b * NPIX + p;
        float v = tile[tx][ty + i * 8] * g_rnorm[tok] * (gamma[c] + 1.0f);
        g_xn[(size_t)tok * DIM + c] = __float2half(v);
    }
}

// fill mem-KV rows 0..3 and zero-pad rows 1028..1087 of K / V
__global__ void init_kv_kernel(const float* __restrict__ mem_kv) {
    int z = blockIdx.x;              // b*8+h
    int h = z & 7;
    __half* kz = g_k + (size_t)z * KVP * DH;
    __half* vz = g_v + (size_t)z * KVP * DH;
    for (int idx = threadIdx.x; idx < NMEM * DH; idx += blockDim.x) {
        int j = idx >> 6, d = idx & 63;
        kz[(size_t)j * DH + d] = __float2half(mem_kv[(0 * HEADS + h) * NMEM * DH + j * DH + d]);
        vz[(size_t)j * DH + d] = __float2half(mem_kv[(1 * HEADS + h) * NMEM * DH + j * DH + d]);
    }
    for (int idx = threadIdx.x; idx < (KVP - KV) * DH; idx += blockDim.x) {
        int j = KV + idx / DH, d = idx % DH;
        kz[(size_t)j * DH + d] = __float2half(0.f);
        vz[(size_t)j * DH + d] = __float2half(0.f);
    }
}

// ------- pipelined WMMA GEMM: C[m][n] = sum_k A[m][k]*B[n][k], K=512 -------
// BM=128, BN=128, BK=32. 3-stage cp.async ring, ONE barrier per slab.
#define SLD 40                        // smem row stride in halfs (80B)
#define GSTG (128 * SLD * 2)          // 10240 B per A or B per stage
#define GSMEM (3 * 2 * GSTG)          // 61440 B

// EP: 0 = qkv scatter, 3 = final out (transposed, coalesced along p)
template<int EP>
__global__ void __launch_bounds__(256) gemm_kernel(float* __restrict__ Cout) {
    extern __shared__ __align__(16) unsigned char dyn[];
    __half* As[3] = { (__half*)(dyn),
                      (__half*)(dyn + 2 * GSTG),
                      (__half*)(dyn + 4 * GSTG) };
    __half* Bs[3] = { (__half*)(dyn + GSTG),
                      (__half*)(dyn + 3 * GSTG),
                      (__half*)(dyn + 5 * GSTG) };

    const __half* A = (EP == 0) ? g_xn  : g_att;
    const __half* B = (EP == 0) ? g_wqkv : g_wout;

    int bm  = blockIdx.y * 128;
    int bn  = blockIdx.x * 128;
    int tid = threadIdx.x;
    int wid = tid >> 5, lane = tid & 31;
    int wm  = (wid >> 1) * 32;
    int wn  = (wid & 1) * 64;

    wmma::fragment<wmma::accumulator, 16, 16, 16, float> fc[2][4];
#pragma unroll
    for (int i = 0; i < 2; i++)
#pragma unroll
        for (int j = 0; j < 4; j++)
            wmma::fill_fragment(fc[i][j], 0.0f);

    const int NK = 512 / 32;   // 16 slabs
    int lr = tid >> 2, lcv = tid & 3;
    const __half* Ar0 = A + (size_t)(bm + lr) * 512 + lcv * 8;
    const __half* Ar1 = A + (size_t)(bm + lr + 64) * 512 + lcv * 8;
    const __half* Br0 = B + (size_t)(bn + lr) * 512 + lcv * 8;
    const __half* Br1 = B + (size_t)(bn + lr + 64) * 512 + lcv * 8;

    // preload slabs 0 and 1
#pragma unroll
    for (int s = 0; s < 2; s++) {
        int k0 = s * 32;
        cp16(&As[s][lr * SLD + lcv * 8],        Ar0 + k0);
        cp16(&As[s][(lr + 64) * SLD + lcv * 8], Ar1 + k0);
        cp16(&Bs[s][lr * SLD + lcv * 8],        Br0 + k0);
        cp16(&Bs[s][(lr + 64) * SLD + lcv * 8], Br1 + k0);
        CP_COMMIT();
    }

#pragma unroll 1
    for (int ks = 0; ks < NK; ks++) {
        if (ks < NK - 1) CP_WAIT(1); else CP_WAIT(0);
        __syncthreads();
        // refill the stage consumed at ks-1 (safe: everyone passed the sync)
        if (ks + 2 < NK) {
            int st = (ks + 2) % 3, k0 = (ks + 2) * 32;
            cp16(&As[st][lr * SLD + lcv * 8],        Ar0 + k0);
            cp16(&As[st][(lr + 64) * SLD + lcv * 8], Ar1 + k0);
            cp16(&Bs[st][lr * SLD + lcv * 8],        Br0 + k0);
            cp16(&Bs[st][(lr + 64) * SLD + lcv * 8], Br1 + k0);
            CP_COMMIT();
        }
        int buf = ks % 3;
#pragma unroll
        for (int kk = 0; kk < 32; kk += 16) {
            wmma::fragment<wmma::matrix_a, 16, 16, 16, __half, wmma::row_major> fa[2];
            wmma::fragment<wmma::matrix_b, 16, 16, 16, __half, wmma::col_major> fb[4];
            wmma::load_matrix_sync(fa[0], &As[buf][(wm + 0)  * SLD + kk], SLD);
            wmma::load_matrix_sync(fa[1], &As[buf][(wm + 16) * SLD + kk], SLD);
#pragma unroll
            for (int j = 0; j < 4; j++)
                wmma::load_matrix_sync(fb[j], &Bs[buf][(wn + j * 16) * SLD + kk], SLD);
#pragma unroll
            for (int i = 0; i < 2; i++)
#pragma unroll
                for (int j = 0; j < 4; j++)
                    wmma::mma_sync(fc[i][j], fa[i], fb[j], fc[i][j]);
        }
    }
    __syncthreads();   // protect smem reuse in epilogue

    // per-warp epilogue: stage each 16x16 frag to warp-private smem, then scatter
    float* Wc = (float*)dyn + wid * 256;
#pragma unroll
    for (int i = 0; i < 2; i++)
#pragma unroll
        for (int j = 0; j < 4; j++) {
            wmma::store_matrix_sync(Wc, fc[i][j], 16, wmma::mem_row_major);
            __syncwarp();
            int m0 = bm + wm + i * 16, n0 = bn + wn + j * 16;
#pragma unroll
            for (int t = 0; t < 8; t++) {
                int e = t * 32 + lane;
                if (EP == 0) {
                    int r = e >> 4, c = e & 15;
                    float v = Wc[r * 16 + c];
                    int m = m0 + r, n = n0 + c;
                    int b = m >> 10, p = m & 1023;
                    if (n < 512) {
                        int h = n >> 6, d = n & 63;
                        g_q[(((size_t)(b * HEADS + h)) * NPIX + p) * DH + d] =
                            __float2half(v * QSCALE);
                    } else if (n < 1024) {
                        int c2 = n - 512; int h = c2 >> 6, d = c2 & 63;
                        g_k[((size_t)(b * HEADS + h) * KVP + NMEM + p) * DH + d] = __float2half(v);
                    } else {
                        int c2 = n - 1024; int h = c2 >> 6, d = c2 & 63;
                        g_v[((size_t)(b * HEADS + h) * KVP + NMEM + p) * DH + d] = __float2half(v);
                    }
                } else {
                    int r = e & 15, c = e >> 4;   // lanes -> rows (p) for coalesced fp32 store
                    float v = Wc[r * 16 + c];
                    int m = m0 + r, n = n0 + c;
                    int b = m >> 10, p = m & 1023;
                    Cout[(size_t)b * DIM * NPIX + (size_t)n * NPIX + p] = v;
                }
            }
            __syncwarp();
        }
}

// ---------------- fused flash attention ----------------
__device__ __forceinline__ void ldsm_x4(uint32_t& r0, uint32_t& r1, uint32_t& r2, uint32_t& r3,
                                        uint32_t a) {
    asm volatile("ldmatrix.sync.aligned.m8n8.x4.shared.b16 {%0,%1,%2,%3},[%4];"
                 : "=r"(r0), "=r"(r1), "=r"(r2), "=r"(r3) : "r"(a));
}
__device__ __forceinline__ void ldsm_x4_t(uint32_t& r0, uint32_t& r1, uint32_t& r2, uint32_t& r3,
                                          uint32_t a) {
    asm volatile("ldmatrix.sync.aligned.m8n8.x4.trans.shared.b16 {%0,%1,%2,%3},[%4];"
                 : "=r"(r0), "=r"(r1), "=r"(r2), "=r"(r3) : "r"(a));
}
__device__ __forceinline__ void mma16816(float* c, const uint32_t* a, const uint32_t* b) {
    asm volatile(
        "mma.sync.aligned.m16n8k16.row.col.f32.f16.f16.f32 "
        "{%0,%1,%2,%3},{%4,%5,%6,%7},{%8,%9},{%0,%1,%2,%3};"
        : "+f"(c[0]), "+f"(c[1]), "+f"(c[2]), "+f"(c[3])
        : "r"(a[0]), "r"(a[1]), "r"(a[2]), "r"(a[3]), "r"(b[0]), "r"(b[1]));
}
__device__ __forceinline__ uint32_t packh2(float a, float b) {
    __half2 h = __floats2half2_rn(a, b);
    return *(uint32_t*)&h;
}
__device__ __forceinline__ uint32_t h2exp2u(uint32_t x) {
    uint32_t r;
    asm("ex2.approx.f16x2 %0, %1;" : "=r"(r) : "r"(x));
    return r;
}
__device__ __forceinline__ float fexp2(float x) {
    float r;
    asm("ex2.approx.ftz.f32 %0, %1;" : "=f"(r) : "f"(x));
    return r;
}

#define FS 72                          // smem row stride in halves (144B)
#define FSTG (64 * FS * 2)             // 9216 B per K or V per stage
#define FSMEM (3 * 2 * FSTG)           // 55296 B

__global__ void __launch_bounds__(256) flash_kernel() {
    extern __shared__ __align__(16) unsigned char fdyn[];
    __half* sQ = (__half*)fdyn;        // aliases the ring before prefetch starts
    __half* sKb[3] = { (__half*)(fdyn),
                       (__half*)(fdyn + 2 * FSTG),
                       (__half*)(fdyn + 4 * FSTG) };
    __half* sVb[3] = { (__half*)(fdyn + FSTG),
                       (__half*)(fdyn + 3 * FSTG),
                       (__half*)(fdyn + 5 * FSTG) };

    int z   = blockIdx.y;
    int m0  = blockIdx.x * 128;
    int tid = threadIdx.x, wid = tid >> 5, lane = tid & 31;

    const __half* Qg = g_q + ((size_t)z * NPIX + m0) * DH;
    const __half* Kg = g_k + (size_t)z * KVP * DH;
    const __half* Vg = g_v + (size_t)z * KVP * DH;

    // load Q tile, build invariant A-fragments, then smem is recycled for K/V
    for (int i = tid; i < 128 * 8; i += 256) {
        int r = i >> 3, cv = i & 7;
        *(uint4*)&sQ[r * FS + cv * 8] = *(const uint4*)&Qg[(size_t)r * DH + cv * 8];
    }
    __syncthreads();

    uint32_t aQ[4][4];
    {
        uint32_t base = smem_u32(&sQ[(wid * 16 + (lane & 15)) * FS + (lane >> 4) * 8]);
#pragma unroll
        for (int kk = 0; kk < 4; kk++)
            ldsm_x4(aQ[kk][0], aQ[kk][1], aQ[kk][2], aQ[kk][3], base + kk * 32);
    }
    __syncthreads();

    float o[8][4];
#pragma unroll
    for (int i = 0; i < 8; i++)
#pragma unroll
        for (int j = 0; j < 4; j++) o[i][j] = 0.f;
    float l_acc[4] = {0.f, 0.f, 0.f, 0.f};    // ones-column accumulator (col 0 = row sum)
    float mrun0 = -1e30f, mrun1 = -1e30f;

    // constant B-fragment for the ones column: B[k][n] = (n==0)
    uint32_t blc = ((lane >> 2) == 0) ? 0x3C003C00u : 0u;
    uint32_t bl[2] = { blc, blc };

    int rowp = ((lane >> 4) & 1) * 8 + (lane & 7);
    int colp = ((lane >> 3) & 1) * 8;
    uint32_t koff = (uint32_t)(rowp * FS + colp) * 2;
    uint32_t voff = (uint32_t)((((lane & 7) + ((lane >> 3) & 1) * 8) * FS
                                + ((lane >> 4) & 1) * 8) * 2);
    uint32_t kbase[3], vbase[3];
#pragma unroll
    for (int s = 0; s < 3; s++) {
        kbase[s] = smem_u32(sKb[s]) + koff;
        vbase[s] = smem_u32(sVb[s]) + voff;
    }

    int ldr = tid >> 2, ldc = (tid & 3) * 2;

    // preload chunks 0 and 1
#pragma unroll
    for (int s = 0; s < 2; s++) {
        int j0 = s * 64;
        cp16(&sKb[s][ldr * FS + ldc * 8],       &Kg[(size_t)(j0 + ldr) * DH + ldc * 8]);
        cp16(&sKb[s][ldr * FS + (ldc + 1) * 8], &Kg[(size_t)(j0 + ldr) * DH + (ldc + 1) * 8]);
        cp16(&sVb[s][ldr * FS + ldc * 8],       &Vg[(size_t)(j0 + ldr) * DH + ldc * 8]);
        cp16(&sVb[s][ldr * FS + (ldc + 1) * 8], &Vg[(size_t)(j0 + ldr) * DH + (ldc + 1) * 8]);
        CP_COMMIT();
    }

#pragma unroll 1
    for (int ch = 0; ch < 17; ch++) {
        if (ch < 16) CP_WAIT(1); else CP_WAIT(0);
        __syncthreads();
        if (ch + 2 < 17) {
            int st = (ch + 2) % 3, j0 = (ch + 2) * 64;
            cp16(&sKb[st][ldr * FS + ldc * 8],       &Kg[(size_t)(j0 + ldr) * DH + ldc * 8]);
            cp16(&sKb[st][ldr * FS + (ldc + 1) * 8], &Kg[(size_t)(j0 + ldr) * DH + (ldc + 1) * 8]);
            cp16(&sVb[st][ldr * FS + ldc * 8],       &Vg[(size_t)(j0 + ldr) * DH + ldc * 8]);
            cp16(&sVb[st][ldr * FS + (ldc + 1) * 8], &Vg[(size_t)(j0 + ldr) * DH + (ldc + 1) * 8]);
            CP_COMMIT();
        }

        int buf = ch % 3;
        uint32_t kb = kbase[buf], vb = vbase[buf];

        // S' = (Q*qscale*log2e) K^T  -- scores already in log2 domain
        float s[8][4];
#pragma unroll
        for (int i = 0; i < 8; i++)
#pragma unroll
            for (int j = 0; j < 4; j++) s[i][j] = 0.f;
#pragma unroll
        for (int kk = 0; kk < 4; kk++)
#pragma unroll
            for (int jnp = 0; jnp < 4; jnp++) {
                uint32_t b[4];
                ldsm_x4(b[0], b[1], b[2], b[3], kb + (jnp * 16 * FS + kk * 16) * 2);
                mma16816(s[2 * jnp], aQ[kk], b);
                mma16816(s[2 * jnp + 1], aQ[kk], b + 2);
            }

        if (ch == 16) {   // mask padded columns j >= 1028
            int q2 = 2 * (lane & 3);
#pragma unroll
            for (int jn = 0; jn < 8; jn++) {
                int j = 1024 + jn * 8 + q2;
                if (j >= KV)     { s[jn][0] = -1e30f; s[jn][2] = -1e30f; }
                if (j + 1 >= KV) { s[jn][1] = -1e30f; s[jn][3] = -1e30f; }
            }
        }

        // online softmax (log2 domain)
        float mc0 = -1e30f, mc1 = -1e30f;
#pragma unroll
        for (int jn = 0; jn < 8; jn++) {
            mc0 = fmaxf(mc0, fmaxf(s[jn][0], s[jn][1]));
            mc1 = fmaxf(mc1, fmaxf(s[jn][2], s[jn][3]));
        }
        mc0 = fmaxf(mc0, __shfl_xor_sync(0xFFFFFFFF, mc0, 1));
        mc0 = fmaxf(mc0, __shfl_xor_sync(0xFFFFFFFF, mc0, 2));
        mc1 = fmaxf(mc1, __shfl_xor_sync(0xFFFFFFFF, mc1, 1));
        mc1 = fmaxf(mc1, __shfl_xor_sync(0xFFFFFFFF, mc1, 2));

        float mn0 = fmaxf(mrun0, mc0), mn1 = fmaxf(mrun1, mc1);
        bool chg = (mn0 != mrun0) || (mn1 != mrun1);
        if (__any_sync(0xFFFFFFFF, chg)) {
            float al0 = fexp2(mrun0 - mn0), al1 = fexp2(mrun1 - mn1);
#pragma unroll
            for (int dn = 0; dn < 8; dn++) {
                o[dn][0] *= al0; o[dn][1] *= al0;
                o[dn][2] *= al1; o[dn][3] *= al1;
            }
            l_acc[0] *= al0; l_acc[2] *= al1;
        }
        mrun0 = mn0; mrun1 = mn1;

        // P = 2^(s' - mn) directly in packed fp16
        uint32_t aP[4][4];
#pragma unroll
        for (int jnp = 0; jnp < 4; jnp++) {
            aP[jnp][0] = h2exp2u(packh2(s[2 * jnp][0] - mn0, s[2 * jnp][1] - mn0));
            aP[jnp][1] = h2exp2u(packh2(s[2 * jnp][2] - mn1, s[2 * jnp][3] - mn1));
            aP[jnp][2] = h2exp2u(packh2(s[2 * jnp + 1][0] - mn0, s[2 * jnp + 1][1] - mn0));
            aP[jnp][3] = h2exp2u(packh2(s[2 * jnp + 1][2] - mn1, s[2 * jnp + 1][3] - mn1));
        }

        // row-sum l accumulates as an extra "ones" output column (exact fp32 accum)
#pragma unroll
        for (int kp = 0; kp < 4; kp++)
            mma16816(l_acc, aP[kp], bl);

        // O += P V
#pragma unroll
        for (int kp = 0; kp < 4; kp++)
#pragma unroll
            for (int dnp = 0; dnp < 4; dnp++) {
                uint32_t b[4];
                ldsm_x4_t(b[0], b[1], b[2], b[3], vb + (kp * 16 * FS + dnp * 16) * 2);
                mma16816(o[2 * dnp], aP[kp], b);
                mma16816(o[2 * dnp + 1], aP[kp], b + 2);
            }
    }

    // broadcast row sums within each 4-lane group, normalize, write out
    int src = lane & 28;
    float l0 = __shfl_sync(0xFFFFFFFF, l_acc[0], src);
    float l1 = __shfl_sync(0xFFFFFFFF, l_acc[2], src);
    float inv0 = 1.f / l0, inv1 = 1.f / l1;
    int b = z >> 3, h = z & 7;
    int r0 = m0 + wid * 16 + (lane >> 2);
    __half* outp = g_att + ((size_t)(b * NPIX + r0)) * HID + h * DH + 2 * (lane & 3);
#pragma unroll
    for (int dn = 0; dn < 8; dn++) {
        __half2 v0 = __floats2half2_rn(o[dn][0] * inv0, o[dn][1] * inv0);
        __half2 v1 = __floats2half2_rn(o[dn][2] * inv1, o[dn][3] * inv1);
        *(__half2*)(outp + dn * 8) = v0;
        *(__half2*)(outp + dn * 8 + (size_t)8 * HID) = v1;
    }
}

// ---------------- launcher ----------------
extern "C" void kernel_launch(void* const* d_in, const int* in_sizes, int n_in,
                              void* d_out, int out_size) {
    const float* x      = (const float*)d_in[0];
    const float* gamma  = (const float*)d_in[1];
    const float* mem_kv = (const float*)d_in[2];
    const float* w_qkv  = (const float*)d_in[3];
    const float* w_out  = (const float*)d_in[4];
    float* out = (float*)d_out;

    cudaFuncSetAttribute(gemm_kernel<0>, cudaFuncAttributeMaxDynamicSharedMemorySize, GSMEM);
    cudaFuncSetAttribute(gemm_kernel<3>, cudaFuncAttributeMaxDynamicSharedMemorySize, GSMEM);
    cudaFuncSetAttribute(flash_kernel,   cudaFuncAttributeMaxDynamicSharedMemorySize, FSMEM);

    cvt_w_kernel<<<(QKV3 * DIM + DIM * HID) / 256, 256>>>(w_qkv, w_out);
    norm_kernel<<<NTOK / 256, 256>>>(x);
    norm_apply_kernel<<<dim3(DIM / 32, NPIX / 32, BATCH), dim3(32, 8)>>>(x, gamma);
    init_kv_kernel<<<ZBH, 256>>>(mem_kv);

    // GEMM1: qkv projection [16384 x 1536 x 512] -> scatter to q/k/v
    gemm_kernel<0><<<dim3(QKV3 / 128, NTOK / 128), 256, GSMEM>>>(nullptr);
    // fused flash attention: per (z, 128-query tile)
    flash_kernel<<<dim3(NPIX / 128, ZBH), 256, FSMEM>>>();
    // GEMM4: out projection [16384 x 512 x 512] -> transposed fp32 write
    gemm_kernel<3><<<dim3(HID / 128, NTOK / 128), 256, GSMEM>>>(out);
}

// round 10
// speedup vs baseline: 3.0160x; 1.0308x over previous
#include <cuda_runtime.h>
#include <cuda_fp16.h>
#include <mma.h>
#include <cstdint>

using namespace nvcuda;

#define HEADS 8
#define DH    64
#define NMEM  4
#define DIM   512
#define BATCH 16
#define NPIX  1024            // 32*32
#define NTOK  (BATCH*NPIX)    // 16384
#define KV    1028            // 4 mem + 1024 tokens
#define KVP   1088            // padded to 17*64
#define QKV3  1536
#define HID   512
#define ZBH   (BATCH*HEADS)   // 128

// Q pre-scale: (1/sqrt(64)) * log2(e), so softmax runs in the 2^x domain
#define QSCALE 0.1803368801111204f

// ---------------- scratch (static device allocations) ----------------
__device__ __align__(16) __half g_xn  [(size_t)NTOK*DIM];
__device__ __align__(16) __half g_wqkv[(size_t)QKV3*DIM];
__device__ __align__(16) __half g_wout[(size_t)DIM*HID];
__device__ __align__(16) __half g_q   [(size_t)ZBH*NPIX*DH];
__device__ __align__(16) __half g_k   [(size_t)ZBH*KVP*DH];
__device__ __align__(16) __half g_v   [(size_t)ZBH*KVP*DH];   // [z][j][d]
__device__ __align__(16) __half g_att [(size_t)NTOK*HID];

// ---------------- async copy helpers ----------------
__device__ __forceinline__ uint32_t smem_u32(const void* p) {
    return (uint32_t)__cvta_generic_to_shared(p);
}
__device__ __forceinline__ void cp16(void* dst, const void* src) {
    asm volatile("cp.async.cg.shared.global [%0],[%1],16;"
                 :: "r"(smem_u32(dst)), "l"(src));
}
#define CP_COMMIT() asm volatile("cp.async.commit_group;")
#define CP_WAIT(n)  asm volatile("cp.async.wait_group %0;" :: "n"(n))

// ---------------- small prep kernels ----------------
__global__ void cvt_w_kernel(const float* __restrict__ wq, const float* __restrict__ wo) {
    int i = blockIdx.x * 256 + threadIdx.x;
    if (i < QKV3 * DIM) g_wqkv[i] = __float2half(wq[i]);
    else {
        int j = i - QKV3 * DIM;
        g_wout[j] = __float2half(wo[j]);
    }
}

// fused RMSNorm: stage x[b, :, p0:p0+32] in smem, compute 32 token norms,
// write xn[token][c] fp16 (single read of x instead of two)
#define NA_SMEM (512 * 33 * 4 + 512 * 4 + 32 * 4)   // tile + gamma + rnorm = 69760 B
__global__ void __launch_bounds__(256) norm_fused_kernel(const float* __restrict__ x,
                                                         const float* __restrict__ gamma) {
    extern __shared__ float ns[];
    float* tile = ns;               // [512][33]
    float* gam  = ns + 512 * 33;    // 512
    float* rno  = gam + 512;        // 32
    int b = blockIdx.y, p0 = blockIdx.x * 32;
    int tid = threadIdx.x;
    const float* xb = x + (size_t)b * DIM * NPIX + p0;

    for (int i = tid; i < 512 * 32; i += 256) {
        int c = i >> 5, p = i & 31;
        tile[c * 33 + p] = xb[(size_t)c * NPIX + p];
    }
    for (int i = tid; i < 512; i += 256) gam[i] = gamma[i] + 1.0f;
    __syncthreads();

    // per-token sum of squares: 8 threads per token
    int tok = tid >> 3, j = tid & 7;
    float s = 0.f;
#pragma unroll 8
    for (int c = j; c < 512; c += 8) {
        float v = tile[c * 33 + tok];
        s += v * v;
    }
    s += __shfl_xor_sync(0xFFFFFFFF, s, 1);
    s += __shfl_xor_sync(0xFFFFFFFF, s, 2);
    s += __shfl_xor_sync(0xFFFFFFFF, s, 4);
    if (j == 0) rno[tok] = 22.62741699796952f / fmaxf(sqrtf(s), 1e-12f);
    __syncthreads();

    __half* outb = g_xn + ((size_t)(b * NPIX + p0)) * DIM;
    for (int i = tid; i < 32 * 256; i += 256) {
        int t = i >> 8, c2 = (i & 255) * 2;
        float r = rno[t];
        __half2 h = __floats2half2_rn(tile[c2 * 33 + t] * r * gam[c2],
                                      tile[(c2 + 1) * 33 + t] * r * gam[c2 + 1]);
        *(__half2*)&outb[(size_t)t * DIM + c2] = h;
    }
}

// fill mem-KV rows 0..3 and zero-pad rows 1028..1087 of K / V
__global__ void init_kv_kernel(const float* __restrict__ mem_kv) {
    int z = blockIdx.x;              // b*8+h
    int h = z & 7;
    __half* kz = g_k + (size_t)z * KVP * DH;
    __half* vz = g_v + (size_t)z * KVP * DH;
    for (int idx = threadIdx.x; idx < NMEM * DH; idx += blockDim.x) {
        int j = idx >> 6, d = idx & 63;
        kz[(size_t)j * DH + d] = __float2half(mem_kv[(0 * HEADS + h) * NMEM * DH + j * DH + d]);
        vz[(size_t)j * DH + d] = __float2half(mem_kv[(1 * HEADS + h) * NMEM * DH + j * DH + d]);
    }
    for (int idx = threadIdx.x; idx < (KVP - KV) * DH; idx += blockDim.x) {
        int j = KV + idx / DH, d = idx % DH;
        kz[(size_t)j * DH + d] = __float2half(0.f);
        vz[(size_t)j * DH + d] = __float2half(0.f);
    }
}

// ------- pipelined WMMA GEMM: C[m][n] = sum_k A[m][k]*B[n][k], K=512 -------
// BM=128, BN=128, BK=32. 3-stage cp.async ring, ONE barrier per slab.
#define SLD 40                        // smem row stride in halfs (80B)
#define GSTG (128 * SLD * 2)          // 10240 B per A or B per stage
#define GSMEM (3 * 2 * GSTG)          // 61440 B

// EP: 0 = qkv scatter, 3 = final out (transposed, coalesced along p)
template<int EP>
__global__ void __launch_bounds__(256) gemm_kernel(float* __restrict__ Cout) {
    extern __shared__ __align__(16) unsigned char dyn[];
    __half* As[3] = { (__half*)(dyn),
                      (__half*)(dyn + 2 * GSTG),
                      (__half*)(dyn + 4 * GSTG) };
    __half* Bs[3] = { (__half*)(dyn + GSTG),
                      (__half*)(dyn + 3 * GSTG),
                      (__half*)(dyn + 5 * GSTG) };

    const __half* A = (EP == 0) ? g_xn  : g_att;
    const __half* B = (EP == 0) ? g_wqkv : g_wout;

    int bm  = blockIdx.y * 128;
    int bn  = blockIdx.x * 128;
    int tid = threadIdx.x;
    int wid = tid >> 5, lane = tid & 31;
    int wm  = (wid >> 1) * 32;
    int wn  = (wid & 1) * 64;

    wmma::fragment<wmma::accumulator, 16, 16, 16, float> fc[2][4];
#pragma unroll
    for (int i = 0; i < 2; i++)
#pragma unroll
        for (int j = 0; j < 4; j++)
            wmma::fill_fragment(fc[i][j], 0.0f);

    const int NK = 512 / 32;   // 16 slabs
    int lr = tid >> 2, lcv = tid & 3;
    const __half* Ar0 = A + (size_t)(bm + lr) * 512 + lcv * 8;
    const __half* Ar1 = A + (size_t)(bm + lr + 64) * 512 + lcv * 8;
    const __half* Br0 = B + (size_t)(bn + lr) * 512 + lcv * 8;
    const __half* Br1 = B + (size_t)(bn + lr + 64) * 512 + lcv * 8;

    // preload slabs 0 and 1
#pragma unroll
    for (int s = 0; s < 2; s++) {
        int k0 = s * 32;
        cp16(&As[s][lr * SLD + lcv * 8],        Ar0 + k0);
        cp16(&As[s][(lr + 64) * SLD + lcv * 8], Ar1 + k0);
        cp16(&Bs[s][lr * SLD + lcv * 8],        Br0 + k0);
        cp16(&Bs[s][(lr + 64) * SLD + lcv * 8], Br1 + k0);
        CP_COMMIT();
    }

#pragma unroll 1
    for (int ks = 0; ks < NK; ks++) {
        if (ks < NK - 1) CP_WAIT(1); else CP_WAIT(0);
        __syncthreads();
        // refill the stage consumed at ks-1 (safe: everyone passed the sync)
        if (ks + 2 < NK) {
            int st = (ks + 2) % 3, k0 = (ks + 2) * 32;
            cp16(&As[st][lr * SLD + lcv * 8],        Ar0 + k0);
            cp16(&As[st][(lr + 64) * SLD + lcv * 8], Ar1 + k0);
            cp16(&Bs[st][lr * SLD + lcv * 8],        Br0 + k0);
            cp16(&Bs[st][(lr + 64) * SLD + lcv * 8], Br1 + k0);
            CP_COMMIT();
        }
        int buf = ks % 3;
#pragma unroll
        for (int kk = 0; kk < 32; kk += 16) {
            wmma::fragment<wmma::matrix_a, 16, 16, 16, __half, wmma::row_major> fa[2];
            wmma::fragment<wmma::matrix_b, 16, 16, 16, __half, wmma::col_major> fb[4];
            wmma::load_matrix_sync(fa[0], &As[buf][(wm + 0)  * SLD + kk], SLD);
            wmma::load_matrix_sync(fa[1], &As[buf][(wm + 16) * SLD + kk], SLD);
#pragma unroll
            for (int j = 0; j < 4; j++)
                wmma::load_matrix_sync(fb[j], &Bs[buf][(wn + j * 16) * SLD + kk], SLD);
#pragma unroll
            for (int i = 0; i < 2; i++)
#pragma unroll
                for (int j = 0; j < 4; j++)
                    wmma::mma_sync(fc[i][j], fa[i], fb[j], fc[i][j]);
        }
    }
    __syncthreads();   // protect smem reuse in epilogue

    // per-warp epilogue: stage each 16x16 frag to warp-private smem, then scatter
    float* Wc = (float*)dyn + wid * 256;
#pragma unroll
    for (int i = 0; i < 2; i++)
#pragma unroll
        for (int j = 0; j < 4; j++) {
            wmma::store_matrix_sync(Wc, fc[i][j], 16, wmma::mem_row_major);
            __syncwarp();
            int m0 = bm + wm + i * 16, n0 = bn + wn + j * 16;
#pragma unroll
            for (int t = 0; t < 8; t++) {
                int e = t * 32 + lane;
                if (EP == 0) {
                    int r = e >> 4, c = e & 15;
                    float v = Wc[r * 16 + c];
                    int m = m0 + r, n = n0 + c;
                    int b = m >> 10, p = m & 1023;
                    if (n < 512) {
                        int h = n >> 6, d = n & 63;
                        g_q[(((size_t)(b * HEADS + h)) * NPIX + p) * DH + d] =
                            __float2half(v * QSCALE);
                    } else if (n < 1024) {
                        int c2 = n - 512; int h = c2 >> 6, d = c2 & 63;
                        g_k[((size_t)(b * HEADS + h) * KVP + NMEM + p) * DH + d] = __float2half(v);
                    } else {
                        int c2 = n - 1024; int h = c2 >> 6, d = c2 & 63;
                        g_v[((size_t)(b * HEADS + h) * KVP + NMEM + p) * DH + d] = __float2half(v);
                    }
                } else {
                    int r = e & 15, c = e >> 4;   // lanes -> rows (p) for coalesced fp32 store
                    float v = Wc[r * 16 + c];
                    int m = m0 + r, n = n0 + c;
                    int b = m >> 10, p = m & 1023;
                    Cout[(size_t)b * DIM * NPIX + (size_t)n * NPIX + p] = v;
                }
            }
            __syncwarp();
        }
}

// ---------------- fused flash attention ----------------
__device__ __forceinline__ void ldsm_x4(uint32_t& r0, uint32_t& r1, uint32_t& r2, uint32_t& r3,
                                        uint32_t a) {
    asm volatile("ldmatrix.sync.aligned.m8n8.x4.shared.b16 {%0,%1,%2,%3},[%4];"
                 : "=r"(r0), "=r"(r1), "=r"(r2), "=r"(r3) : "r"(a));
}
__device__ __forceinline__ void ldsm_x4_t(uint32_t& r0, uint32_t& r1, uint32_t& r2, uint32_t& r3,
                                          uint32_t a) {
    asm volatile("ldmatrix.sync.aligned.m8n8.x4.trans.shared.b16 {%0,%1,%2,%3},[%4];"
                 : "=r"(r0), "=r"(r1), "=r"(r2), "=r"(r3) : "r"(a));
}
__device__ __forceinline__ void mma16816(float* c, const uint32_t* a, const uint32_t* b) {
    asm volatile(
        "mma.sync.aligned.m16n8k16.row.col.f32.f16.f16.f32 "
        "{%0,%1,%2,%3},{%4,%5,%6,%7},{%8,%9},{%0,%1,%2,%3};"
        : "+f"(c[0]), "+f"(c[1]), "+f"(c[2]), "+f"(c[3])
        : "r"(a[0]), "r"(a[1]), "r"(a[2]), "r"(a[3]), "r"(b[0]), "r"(b[1]));
}
__device__ __forceinline__ uint32_t packh2(float a, float b) {
    __half2 h = __floats2half2_rn(a, b);
    return *(uint32_t*)&h;
}
__device__ __forceinline__ uint32_t h2exp2u(uint32_t x) {
    uint32_t r;
    asm("ex2.approx.f16x2 %0, %1;" : "=r"(r) : "r"(x));
    return r;
}
__device__ __forceinline__ float fexp2(float x) {
    float r;
    asm("ex2.approx.ftz.f32 %0, %1;" : "=f"(r) : "f"(x));
    return r;
}

#define FS 72                          // smem row stride in halves (144B)
#define FSTG (64 * FS * 2)             // 9216 B per K or V per stage
#define FSMEM (3 * 2 * FSTG)           // 55296 B

__global__ void __launch_bounds__(256, 2) flash_kernel() {
    extern __shared__ __align__(16) unsigned char fdyn[];
    __half* sQ = (__half*)fdyn;        // aliases the ring before prefetch starts
    __half* sKb[3] = { (__half*)(fdyn),
                       (__half*)(fdyn + 2 * FSTG),
                       (__half*)(fdyn + 4 * FSTG) };
    __half* sVb[3] = { (__half*)(fdyn + FSTG),
                       (__half*)(fdyn + 3 * FSTG),
                       (__half*)(fdyn + 5 * FSTG) };

    int z   = blockIdx.y;
    int m0  = blockIdx.x * 128;
    int tid = threadIdx.x, wid = tid >> 5, lane = tid & 31;

    const __half* Qg = g_q + ((size_t)z * NPIX + m0) * DH;
    const __half* Kg = g_k + (size_t)z * KVP * DH;
    const __half* Vg = g_v + (size_t)z * KVP * DH;

    // load Q tile, build invariant A-fragments, then smem is recycled for K/V
    for (int i = tid; i < 128 * 8; i += 256) {
        int r = i >> 3, cv = i & 7;
        *(uint4*)&sQ[r * FS + cv * 8] = *(const uint4*)&Qg[(size_t)r * DH + cv * 8];
    }
    __syncthreads();

    uint32_t aQ[4][4];
    {
        uint32_t base = smem_u32(&sQ[(wid * 16 + (lane & 15)) * FS + (lane >> 4) * 8]);
#pragma unroll
        for (int kk = 0; kk < 4; kk++)
            ldsm_x4(aQ[kk][0], aQ[kk][1], aQ[kk][2], aQ[kk][3], base + kk * 32);
    }
    __syncthreads();

    float o[8][4];
#pragma unroll
    for (int i = 0; i < 8; i++)
#pragma unroll
        for (int j = 0; j < 4; j++) o[i][j] = 0.f;
    float l_acc[4] = {0.f, 0.f, 0.f, 0.f};    // ones-column accumulator (col 0 = row sum)
    float mrun0 = -1e30f, mrun1 = -1e30f;

    // constant B-fragment for the ones column: B[k][n] = (n==0)
    uint32_t blc = ((lane >> 2) == 0) ? 0x3C003C00u : 0u;
    uint32_t bl[2] = { blc, blc };

    int rowp = ((lane >> 4) & 1) * 8 + (lane & 7);
    int colp = ((lane >> 3) & 1) * 8;
    uint32_t koff = (uint32_t)(rowp * FS + colp) * 2;
    uint32_t voff = (uint32_t)((((lane & 7) + ((lane >> 3) & 1) * 8) * FS
                                + ((lane >> 4) & 1) * 8) * 2);
    uint32_t kbase[3], vbase[3];
#pragma unroll
    for (int s = 0; s < 3; s++) {
        kbase[s] = smem_u32(sKb[s]) + koff;
        vbase[s] = smem_u32(sVb[s]) + voff;
    }

    int ldr = tid >> 2, ldc = (tid & 3) * 2;

    // preload chunks 0 and 1
#pragma unroll
    for (int s = 0; s < 2; s++) {
        int j0 = s * 64;
        cp16(&sKb[s][ldr * FS + ldc * 8],       &Kg[(size_t)(j0 + ldr) * DH + ldc * 8]);
        cp16(&sKb[s][ldr * FS + (ldc + 1) * 8], &Kg[(size_t)(j0 + ldr) * DH + (ldc + 1) * 8]);
        cp16(&sVb[s][ldr * FS + ldc * 8],       &Vg[(size_t)(j0 + ldr) * DH + ldc * 8]);
        cp16(&sVb[s][ldr * FS + (ldc + 1) * 8], &Vg[(size_t)(j0 + ldr) * DH + (ldc + 1) * 8]);
        CP_COMMIT();
    }

#pragma unroll 1
    for (int ch = 0; ch < 17; ch++) {
        if (ch < 16) CP_WAIT(1); else CP_WAIT(0);
        __syncthreads();
        if (ch + 2 < 17) {
            int st = (ch + 2) % 3, j0 = (ch + 2) * 64;
            cp16(&sKb[st][ldr * FS + ldc * 8],       &Kg[(size_t)(j0 + ldr) * DH + ldc * 8]);
            cp16(&sKb[st][ldr * FS + (ldc + 1) * 8], &Kg[(size_t)(j0 + ldr) * DH + (ldc + 1) * 8]);
            cp16(&sVb[st][ldr * FS + ldc * 8],       &Vg[(size_t)(j0 + ldr) * DH + ldc * 8]);
            cp16(&sVb[st][ldr * FS + (ldc + 1) * 8], &Vg[(size_t)(j0 + ldr) * DH + (ldc + 1) * 8]);
            CP_COMMIT();
        }

        int buf = ch % 3;
        uint32_t kb = kbase[buf], vb = vbase[buf];

        // S' = (Q*qscale*log2e) K^T  -- scores already in log2 domain
        float s[8][4];
#pragma unroll
        for (int i = 0; i < 8; i++)
#pragma unroll
            for (int j = 0; j < 4; j++) s[i][j] = 0.f;
#pragma unroll
        for (int kk = 0; kk < 4; kk++)
#pragma unroll
            for (int jnp = 0; jnp < 4; jnp++) {
                uint32_t b[4];
                ldsm_x4(b[0], b[1], b[2], b[3], kb + (jnp * 16 * FS + kk * 16) * 2);
                mma16816(s[2 * jnp], aQ[kk], b);
                mma16816(s[2 * jnp + 1], aQ[kk], b + 2);
            }

        if (ch == 16) {   // mask padded columns j >= 1028
            int q2 = 2 * (lane & 3);
#pragma unroll
            for (int jn = 0; jn < 8; jn++) {
                int j = 1024 + jn * 8 + q2;
                if (j >= KV)     { s[jn][0] = -1e30f; s[jn][2] = -1e30f; }
                if (j + 1 >= KV) { s[jn][1] = -1e30f; s[jn][3] = -1e30f; }
            }
        }

        // online softmax (log2 domain)
        float mc0 = -1e30f, mc1 = -1e30f;
#pragma unroll
        for (int jn = 0; jn < 8; jn++) {
            mc0 = fmaxf(mc0, fmaxf(s[jn][0], s[jn][1]));
            mc1 = fmaxf(mc1, fmaxf(s[jn][2], s[jn][3]));
        }
        mc0 = fmaxf(mc0, __shfl_xor_sync(0xFFFFFFFF, mc0, 1));
        mc0 = fmaxf(mc0, __shfl_xor_sync(0xFFFFFFFF, mc0, 2));
        mc1 = fmaxf(mc1, __shfl_xor_sync(0xFFFFFFFF, mc1, 1));
        mc1 = fmaxf(mc1, __shfl_xor_sync(0xFFFFFFFF, mc1, 2));

        float mn0 = fmaxf(mrun0, mc0), mn1 = fmaxf(mrun1, mc1);
        bool chg = (mn0 != mrun0) || (mn1 != mrun1);
        if (__any_sync(0xFFFFFFFF, chg)) {
            float al0 = fexp2(mrun0 - mn0), al1 = fexp2(mrun1 - mn1);
#pragma unroll
            for (int dn = 0; dn < 8; dn++) {
                o[dn][0] *= al0; o[dn][1] *= al0;
                o[dn][2] *= al1; o[dn][3] *= al1;
            }
            l_acc[0] *= al0; l_acc[2] *= al1;
        }
        mrun0 = mn0; mrun1 = mn1;

        // P = 2^(s' - mn) directly in packed fp16
        uint32_t aP[4][4];
#pragma unroll
        for (int jnp = 0; jnp < 4; jnp++) {
            aP[jnp][0] = h2exp2u(packh2(s[2 * jnp][0] - mn0, s[2 * jnp][1] - mn0));
            aP[jnp][1] = h2exp2u(packh2(s[2 * jnp][2] - mn1, s[2 * jnp][3] - mn1));
            aP[jnp][2] = h2exp2u(packh2(s[2 * jnp + 1][0] - mn0, s[2 * jnp + 1][1] - mn0));
            aP[jnp][3] = h2exp2u(packh2(s[2 * jnp + 1][2] - mn1, s[2 * jnp + 1][3] - mn1));
        }

        // row-sum l accumulates as an extra "ones" output column (exact fp32 accum)
#pragma unroll
        for (int kp = 0; kp < 4; kp++)
            mma16816(l_acc, aP[kp], bl);

        // O += P V
#pragma unroll
        for (int kp = 0; kp < 4; kp++)
#pragma unroll
            for (int dnp = 0; dnp < 4; dnp++) {
                uint32_t b[4];
                ldsm_x4_t(b[0], b[1], b[2], b[3], vb + (kp * 16 * FS + dnp * 16) * 2);
                mma16816(o[2 * dnp], aP[kp], b);
                mma16816(o[2 * dnp + 1], aP[kp], b + 2);
            }
    }

    // broadcast row sums within each 4-lane group, normalize, write out
    int src = lane & 28;
    float l0 = __shfl_sync(0xFFFFFFFF, l_acc[0], src);
    float l1 = __shfl_sync(0xFFFFFFFF, l_acc[2], src);
    float inv0 = 1.f / l0, inv1 = 1.f / l1;
    int b = z >> 3, h = z & 7;
    int r0 = m0 + wid * 16 + (lane >> 2);
    __half* outp = g_att + ((size_t)(b * NPIX + r0)) * HID + h * DH + 2 * (lane & 3);
#pragma unroll
    for (int dn = 0; dn < 8; dn++) {
        __half2 v0 = __floats2half2_rn(o[dn][0] * inv0, o[dn][1] * inv0);
        __half2 v1 = __floats2half2_rn(o[dn][2] * inv1, o[dn][3] * inv1);
        *(__half2*)(outp + dn * 8) = v0;
        *(__half2*)(outp + dn * 8 + (size_t)8 * HID) = v1;
    }
}

// ---------------- launcher ----------------
extern "C" void kernel_launch(void* const* d_in, const int* in_sizes, int n_in,
                              void* d_out, int out_size) {
    const float* x      = (const float*)d_in[0];
    const float* gamma  = (const float*)d_in[1];
    const float* mem_kv = (const float*)d_in[2];
    const float* w_qkv  = (const float*)d_in[3];
    const float* w_out  = (const float*)d_in[4];
    float* out = (float*)d_out;

    cudaFuncSetAttribute(gemm_kernel<0>, cudaFuncAttributeMaxDynamicSharedMemorySize, GSMEM);
    cudaFuncSetAttribute(gemm_kernel<3>, cudaFuncAttributeMaxDynamicSharedMemorySize, GSMEM);
    cudaFuncSetAttribute(flash_kernel,   cudaFuncAttributeMaxDynamicSharedMemorySize, FSMEM);
    cudaFuncSetAttribute(norm_fused_kernel, cudaFuncAttributeMaxDynamicSharedMemorySize, NA_SMEM);

    cvt_w_kernel<<<(QKV3 * DIM + DIM * HID) / 256, 256>>>(w_qkv, w_out);
    norm_fused_kernel<<<dim3(NPIX / 32, BATCH), 256, NA_SMEM>>>(x, gamma);
    init_kv_kernel<<<ZBH, 256>>>(mem_kv);

    // GEMM1: qkv projection [16384 x 1536 x 512] -> scatter to q/k/v
    gemm_kernel<0><<<dim3(QKV3 / 128, NTOK / 128), 256, GSMEM>>>(nullptr);
    // fused flash attention: per (z, 128-query tile)
    flash_kernel<<<dim3(NPIX / 128, ZBH), 256, FSMEM>>>();
    // GEMM4: out projection [16384 x 512 x 512] -> transposed fp32 write
    gemm_kernel<3><<<dim3(HID / 128, NTOK / 128), 256, GSMEM>>>(out);
}

// round 11
// speedup vs baseline: 3.0198x; 1.0012x over previous
#include <cuda_runtime.h>
#include <cuda_fp16.h>
#include <mma.h>
#include <cstdint>

using namespace nvcuda;

#define HEADS 8
#define DH    64
#define NMEM  4
#define DIM   512
#define BATCH 16
#define NPIX  1024            // 32*32
#define NTOK  (BATCH*NPIX)    // 16384
#define KV    1028            // 4 mem + 1024 tokens
#define KVP   1088            // padded to 17*64
#define QKV3  1536
#define HID   512
#define ZBH   (BATCH*HEADS)   // 128

// Q pre-scale: (1/sqrt(64)) * log2(e), so softmax runs in the 2^x domain
#define QSCALE 0.1803368801111204f

// ---------------- scratch (static device allocations) ----------------
__device__ __align__(16) __half g_xn  [(size_t)NTOK*DIM];
__device__ __align__(16) __half g_wqkv[(size_t)QKV3*DIM];
__device__ __align__(16) __half g_wout[(size_t)DIM*HID];
__device__ __align__(16) __half g_q   [(size_t)ZBH*NPIX*DH];
__device__ __align__(16) __half g_k   [(size_t)ZBH*KVP*DH];
__device__ __align__(16) __half g_v   [(size_t)ZBH*KVP*DH];   // [z][j][d]
__device__ __align__(16) __half g_att [(size_t)NTOK*HID];

// ---------------- async copy helpers ----------------
__device__ __forceinline__ uint32_t smem_u32(const void* p) {
    return (uint32_t)__cvta_generic_to_shared(p);
}
__device__ __forceinline__ void cp16(void* dst, const void* src) {
    asm volatile("cp.async.cg.shared.global [%0],[%1],16;"
                 :: "r"(smem_u32(dst)), "l"(src));
}
#define CP_COMMIT() asm volatile("cp.async.commit_group;")
#define CP_WAIT(n)  asm volatile("cp.async.wait_group %0;" :: "n"(n))

// ---------------- small prep kernels ----------------
__global__ void cvt_w_kernel(const float* __restrict__ wq, const float* __restrict__ wo) {
    int i = blockIdx.x * 256 + threadIdx.x;
    if (i < QKV3 * DIM) g_wqkv[i] = __float2half(wq[i]);
    else {
        int j = i - QKV3 * DIM;
        g_wout[j] = __float2half(wo[j]);
    }
}

// fused RMSNorm: stage x[b, :, p0:p0+32] in smem, compute 32 token norms,
// write xn[token][c] fp16 (single read of x instead of two)
#define NA_SMEM (512 * 33 * 4 + 512 * 4 + 32 * 4)   // tile + gamma + rnorm = 69760 B
__global__ void __launch_bounds__(256) norm_fused_kernel(const float* __restrict__ x,
                                                         const float* __restrict__ gamma) {
    extern __shared__ float ns[];
    float* tile = ns;               // [512][33]
    float* gam  = ns + 512 * 33;    // 512
    float* rno  = gam + 512;        // 32
    int b = blockIdx.y, p0 = blockIdx.x * 32;
    int tid = threadIdx.x;
    const float* xb = x + (size_t)b * DIM * NPIX + p0;

    for (int i = tid; i < 512 * 32; i += 256) {
        int c = i >> 5, p = i & 31;
        tile[c * 33 + p] = xb[(size_t)c * NPIX + p];
    }
    for (int i = tid; i < 512; i += 256) gam[i] = gamma[i] + 1.0f;
    __syncthreads();

    // per-token sum of squares: 8 threads per token
    int tok = tid >> 3, j = tid & 7;
    float s = 0.f;
#pragma unroll 8
    for (int c = j; c < 512; c += 8) {
        float v = tile[c * 33 + tok];
        s += v * v;
    }
    s += __shfl_xor_sync(0xFFFFFFFF, s, 1);
    s += __shfl_xor_sync(0xFFFFFFFF, s, 2);
    s += __shfl_xor_sync(0xFFFFFFFF, s, 4);
    if (j == 0) rno[tok] = 22.62741699796952f / fmaxf(sqrtf(s), 1e-12f);
    __syncthreads();

    __half* outb = g_xn + ((size_t)(b * NPIX + p0)) * DIM;
    for (int i = tid; i < 32 * 256; i += 256) {
        int t = i >> 8, c2 = (i & 255) * 2;
        float r = rno[t];
        __half2 h = __floats2half2_rn(tile[c2 * 33 + t] * r * gam[c2],
                                      tile[(c2 + 1) * 33 + t] * r * gam[c2 + 1]);
        *(__half2*)&outb[(size_t)t * DIM + c2] = h;
    }
}

// fill mem-KV rows 0..3 and zero-pad rows 1028..1087 of K / V
__global__ void init_kv_kernel(const float* __restrict__ mem_kv) {
    int z = blockIdx.x;              // b*8+h
    int h = z & 7;
    __half* kz = g_k + (size_t)z * KVP * DH;
    __half* vz = g_v + (size_t)z * KVP * DH;
    for (int idx = threadIdx.x; idx < NMEM * DH; idx += blockDim.x) {
        int j = idx >> 6, d = idx & 63;
        kz[(size_t)j * DH + d] = __float2half(mem_kv[(0 * HEADS + h) * NMEM * DH + j * DH + d]);
        vz[(size_t)j * DH + d] = __float2half(mem_kv[(1 * HEADS + h) * NMEM * DH + j * DH + d]);
    }
    for (int idx = threadIdx.x; idx < (KVP - KV) * DH; idx += blockDim.x) {
        int j = KV + idx / DH, d = idx % DH;
        kz[(size_t)j * DH + d] = __float2half(0.f);
        vz[(size_t)j * DH + d] = __float2half(0.f);
    }
}

// ------- pipelined WMMA GEMM: C[m][n] = sum_k A[m][k]*B[n][k], K=512 -------
// BM=128, BN=128, BK=32. 3-stage cp.async ring, ONE barrier per slab.
#define SLD 40                        // smem row stride in halfs (80B)
#define GSTG (128 * SLD * 2)          // 10240 B per A or B per stage
#define GSMEM (3 * 2 * GSTG)          // 61440 B

// EP: 0 = qkv scatter, 3 = final out (transposed, coalesced along p)
template<int EP>
__global__ void __launch_bounds__(256) gemm_kernel(float* __restrict__ Cout) {
    extern __shared__ __align__(16) unsigned char dyn[];
    __half* As[3] = { (__half*)(dyn),
                      (__half*)(dyn + 2 * GSTG),
                      (__half*)(dyn + 4 * GSTG) };
    __half* Bs[3] = { (__half*)(dyn + GSTG),
                      (__half*)(dyn + 3 * GSTG),
                      (__half*)(dyn + 5 * GSTG) };

    const __half* A = (EP == 0) ? g_xn  : g_att;
    const __half* B = (EP == 0) ? g_wqkv : g_wout;

    int bm  = blockIdx.y * 128;
    int bn  = blockIdx.x * 128;
    int tid = threadIdx.x;
    int wid = tid >> 5, lane = tid & 31;
    int wm  = (wid >> 1) * 32;
    int wn  = (wid & 1) * 64;

    wmma::fragment<wmma::accumulator, 16, 16, 16, float> fc[2][4];
#pragma unroll
    for (int i = 0; i < 2; i++)
#pragma unroll
        for (int j = 0; j < 4; j++)
            wmma::fill_fragment(fc[i][j], 0.0f);

    const int NK = 512 / 32;   // 16 slabs
    int lr = tid >> 2, lcv = tid & 3;
    const __half* Ar0 = A + (size_t)(bm + lr) * 512 + lcv * 8;
    const __half* Ar1 = A + (size_t)(bm + lr + 64) * 512 + lcv * 8;
    const __half* Br0 = B + (size_t)(bn + lr) * 512 + lcv * 8;
    const __half* Br1 = B + (size_t)(bn + lr + 64) * 512 + lcv * 8;

    // preload slabs 0 and 1
#pragma unroll
    for (int s = 0; s < 2; s++) {
        int k0 = s * 32;
        cp16(&As[s][lr * SLD + lcv * 8],        Ar0 + k0);
        cp16(&As[s][(lr + 64) * SLD + lcv * 8], Ar1 + k0);
        cp16(&Bs[s][lr * SLD + lcv * 8],        Br0 + k0);
        cp16(&Bs[s][(lr + 64) * SLD + lcv * 8], Br1 + k0);
        CP_COMMIT();
    }

#pragma unroll 1
    for (int ks = 0; ks < NK; ks++) {
        if (ks < NK - 1) CP_WAIT(1); else CP_WAIT(0);
        __syncthreads();
        // refill the stage consumed at ks-1 (safe: everyone passed the sync)
        if (ks + 2 < NK) {
            int st = (ks + 2) % 3, k0 = (ks + 2) * 32;
            cp16(&As[st][lr * SLD + lcv * 8],        Ar0 + k0);
            cp16(&As[st][(lr + 64) * SLD + lcv * 8], Ar1 + k0);
            cp16(&Bs[st][lr * SLD + lcv * 8],        Br0 + k0);
            cp16(&Bs[st][(lr + 64) * SLD + lcv * 8], Br1 + k0);
            CP_COMMIT();
        }
        int buf = ks % 3;
#pragma unroll
        for (int kk = 0; kk < 32; kk += 16) {
            wmma::fragment<wmma::matrix_a, 16, 16, 16, __half, wmma::row_major> fa[2];
            wmma::fragment<wmma::matrix_b, 16, 16, 16, __half, wmma::col_major> fb[4];
            wmma::load_matrix_sync(fa[0], &As[buf][(wm + 0)  * SLD + kk], SLD);
            wmma::load_matrix_sync(fa[1], &As[buf][(wm + 16) * SLD + kk], SLD);
#pragma unroll
            for (int j = 0; j < 4; j++)
                wmma::load_matrix_sync(fb[j], &Bs[buf][(wn + j * 16) * SLD + kk], SLD);
#pragma unroll
            for (int i = 0; i < 2; i++)
#pragma unroll
                for (int j = 0; j < 4; j++)
                    wmma::mma_sync(fc[i][j], fa[i], fb[j], fc[i][j]);
        }
    }
    __syncthreads();   // protect smem reuse in epilogue

    // per-warp epilogue: stage each 16x16 frag to warp-private smem, then scatter
    float* Wc = (float*)dyn + wid * 256;
#pragma unroll
    for (int i = 0; i < 2; i++)
#pragma unroll
        for (int j = 0; j < 4; j++) {
            wmma::store_matrix_sync(Wc, fc[i][j], 16, wmma::mem_row_major);
            __syncwarp();
            int m0 = bm + wm + i * 16, n0 = bn + wn + j * 16;
#pragma unroll
            for (int t = 0; t < 8; t++) {
                int e = t * 32 + lane;
                if (EP == 0) {
                    int r = e >> 4, c = e & 15;
                    float v = Wc[r * 16 + c];
                    int m = m0 + r, n = n0 + c;
                    int b = m >> 10, p = m & 1023;
                    if (n < 512) {
                        int h = n >> 6, d = n & 63;
                        g_q[(((size_t)(b * HEADS + h)) * NPIX + p) * DH + d] =
                            __float2half(v * QSCALE);
                    } else if (n < 1024) {
                        int c2 = n - 512; int h = c2 >> 6, d = c2 & 63;
                        g_k[((size_t)(b * HEADS + h) * KVP + NMEM + p) * DH + d] = __float2half(v);
                    } else {
                        int c2 = n - 1024; int h = c2 >> 6, d = c2 & 63;
                        g_v[((size_t)(b * HEADS + h) * KVP + NMEM + p) * DH + d] = __float2half(v);
                    }
                } else {
                    int r = e & 15, c = e >> 4;   // lanes -> rows (p) for coalesced fp32 store
                    float v = Wc[r * 16 + c];
                    int m = m0 + r, n = n0 + c;
                    int b = m >> 10, p = m & 1023;
                    Cout[(size_t)b * DIM * NPIX + (size_t)n * NPIX + p] = v;
                }
            }
            __syncwarp();
        }
}

// ---------------- fused flash attention ----------------
__device__ __forceinline__ void ldsm_x4(uint32_t& r0, uint32_t& r1, uint32_t& r2, uint32_t& r3,
                                        uint32_t a) {
    asm volatile("ldmatrix.sync.aligned.m8n8.x4.shared.b16 {%0,%1,%2,%3},[%4];"
                 : "=r"(r0), "=r"(r1), "=r"(r2), "=r"(r3) : "r"(a));
}
__device__ __forceinline__ void ldsm_x4_t(uint32_t& r0, uint32_t& r1, uint32_t& r2, uint32_t& r3,
                                          uint32_t a) {
    asm volatile("ldmatrix.sync.aligned.m8n8.x4.trans.shared.b16 {%0,%1,%2,%3},[%4];"
                 : "=r"(r0), "=r"(r1), "=r"(r2), "=r"(r3) : "r"(a));
}
__device__ __forceinline__ void mma16816(float* c, const uint32_t* a, const uint32_t* b) {
    asm volatile(
        "mma.sync.aligned.m16n8k16.row.col.f32.f16.f16.f32 "
        "{%0,%1,%2,%3},{%4,%5,%6,%7},{%8,%9},{%0,%1,%2,%3};"
        : "+f"(c[0]), "+f"(c[1]), "+f"(c[2]), "+f"(c[3])
        : "r"(a[0]), "r"(a[1]), "r"(a[2]), "r"(a[3]), "r"(b[0]), "r"(b[1]));
}
__device__ __forceinline__ uint32_t packh2(float a, float b) {
    __half2 h = __floats2half2_rn(a, b);
    return *(uint32_t*)&h;
}
__device__ __forceinline__ uint32_t h2exp2u(uint32_t x) {
    uint32_t r;
    asm("ex2.approx.f16x2 %0, %1;" : "=r"(r) : "r"(x));
    return r;
}
__device__ __forceinline__ float fexp2(float x) {
    float r;
    asm("ex2.approx.ftz.f32 %0, %1;" : "=f"(r) : "f"(x));
    return r;
}

#define FS 72                          // smem row stride in halves (144B)
#define FSTG (64 * FS * 2)             // 9216 B per K or V per stage
#define FSMEM (3 * 2 * FSTG)           // 55296 B

__global__ void __launch_bounds__(256, 2) flash_kernel() {
    extern __shared__ __align__(16) unsigned char fdyn[];
    __half* sQ = (__half*)fdyn;        // aliases the ring before prefetch starts
    __half* sKb[3] = { (__half*)(fdyn),
                       (__half*)(fdyn + 2 * FSTG),
                       (__half*)(fdyn + 4 * FSTG) };
    __half* sVb[3] = { (__half*)(fdyn + FSTG),
                       (__half*)(fdyn + 3 * FSTG),
                       (__half*)(fdyn + 5 * FSTG) };

    int z   = blockIdx.y;
    int m0  = blockIdx.x * 128;
    int tid = threadIdx.x, wid = tid >> 5, lane = tid & 31;

    const __half* Qg = g_q + ((size_t)z * NPIX + m0) * DH;
    const __half* Kg = g_k + (size_t)z * KVP * DH;
    const __half* Vg = g_v + (size_t)z * KVP * DH;

    // load Q tile, build invariant A-fragments, then smem is recycled for K/V
    for (int i = tid; i < 128 * 8; i += 256) {
        int r = i >> 3, cv = i & 7;
        *(uint4*)&sQ[r * FS + cv * 8] = *(const uint4*)&Qg[(size_t)r * DH + cv * 8];
    }
    __syncthreads();

    uint32_t aQ[4][4];
    {
        uint32_t base = smem_u32(&sQ[(wid * 16 + (lane & 15)) * FS + (lane >> 4) * 8]);
#pragma unroll
        for (int kk = 0; kk < 4; kk++)
            ldsm_x4(aQ[kk][0], aQ[kk][1], aQ[kk][2], aQ[kk][3], base + kk * 32);
    }
    __syncthreads();

    float o[8][4];
#pragma unroll
    for (int i = 0; i < 8; i++)
#pragma unroll
        for (int j = 0; j < 4; j++) o[i][j] = 0.f;
    float l_acc[4] = {0.f, 0.f, 0.f, 0.f};    // ones-column accumulator (col 0 = row sum)
    float mrun0 = -1e30f, mrun1 = -1e30f;

    // constant B-fragment for the ones column: B[k][n] = (n==0)
    uint32_t blc = ((lane >> 2) == 0) ? 0x3C003C00u : 0u;
    uint32_t bl[2] = { blc, blc };

    int rowp = ((lane >> 4) & 1) * 8 + (lane & 7);
    int colp = ((lane >> 3) & 1) * 8;
    uint32_t koff = (uint32_t)(rowp * FS + colp) * 2;
    uint32_t voff = (uint32_t)((((lane & 7) + ((lane >> 3) & 1) * 8) * FS
                                + ((lane >> 4) & 1) * 8) * 2);
    uint32_t kbase[3], vbase[3];
#pragma unroll
    for (int s = 0; s < 3; s++) {
        kbase[s] = smem_u32(sKb[s]) + koff;
        vbase[s] = smem_u32(sVb[s]) + voff;
    }

    int ldr = tid >> 2, ldc = (tid & 3) * 2;

    // preload chunks 0 and 1
#pragma unroll
    for (int s = 0; s < 2; s++) {
        int j0 = s * 64;
        cp16(&sKb[s][ldr * FS + ldc * 8],       &Kg[(size_t)(j0 + ldr) * DH + ldc * 8]);
        cp16(&sKb[s][ldr * FS + (ldc + 1) * 8], &Kg[(size_t)(j0 + ldr) * DH + (ldc + 1) * 8]);
        cp16(&sVb[s][ldr * FS + ldc * 8],       &Vg[(size_t)(j0 + ldr) * DH + ldc * 8]);
        cp16(&sVb[s][ldr * FS + (ldc + 1) * 8], &Vg[(size_t)(j0 + ldr) * DH + (ldc + 1) * 8]);
        CP_COMMIT();
    }

#pragma unroll 1
    for (int ch = 0; ch < 17; ch++) {
        if (ch < 16) CP_WAIT(1); else CP_WAIT(0);
        __syncthreads();
        if (ch + 2 < 17) {
            int st = (ch + 2) % 3, j0 = (ch + 2) * 64;
            cp16(&sKb[st][ldr * FS + ldc * 8],       &Kg[(size_t)(j0 + ldr) * DH + ldc * 8]);
            cp16(&sKb[st][ldr * FS + (ldc + 1) * 8], &Kg[(size_t)(j0 + ldr) * DH + (ldc + 1) * 8]);
            cp16(&sVb[st][ldr * FS + ldc * 8],       &Vg[(size_t)(j0 + ldr) * DH + ldc * 8]);
            cp16(&sVb[st][ldr * FS + (ldc + 1) * 8], &Vg[(size_t)(j0 + ldr) * DH + (ldc + 1) * 8]);
            CP_COMMIT();
        }

        int buf = ch % 3;
        uint32_t kb = kbase[buf], vb = vbase[buf];

        // S' = (Q*qscale*log2e) K^T  -- scores already in log2 domain
        float s[8][4];
#pragma unroll
        for (int i = 0; i < 8; i++)
#pragma unroll
            for (int j = 0; j < 4; j++) s[i][j] = 0.f;
#pragma unroll
        for (int kk = 0; kk < 4; kk++)
#pragma unroll
            for (int jnp = 0; jnp < 4; jnp++) {
                uint32_t b[4];
                ldsm_x4(b[0], b[1], b[2], b[3], kb + (jnp * 16 * FS + kk * 16) * 2);
                mma16816(s[2 * jnp], aQ[kk], b);
                mma16816(s[2 * jnp + 1], aQ[kk], b + 2);
            }

        if (ch == 16) {   // mask padded columns j >= 1028
            int q2 = 2 * (lane & 3);
#pragma unroll
            for (int jn = 0; jn < 8; jn++) {
                int j = 1024 + jn * 8 + q2;
                if (j >= KV)     { s[jn][0] = -1e30f; s[jn][2] = -1e30f; }
                if (j + 1 >= KV) { s[jn][1] = -1e30f; s[jn][3] = -1e30f; }
            }
        }

        // online softmax (log2 domain)
        float mc0 = -1e30f, mc1 = -1e30f;
#pragma unroll
        for (int jn = 0; jn < 8; jn++) {
            mc0 = fmaxf(mc0, fmaxf(s[jn][0], s[jn][1]));
            mc1 = fmaxf(mc1, fmaxf(s[jn][2], s[jn][3]));
        }
        mc0 = fmaxf(mc0, __shfl_xor_sync(0xFFFFFFFF, mc0, 1));
        mc0 = fmaxf(mc0, __shfl_xor_sync(0xFFFFFFFF, mc0, 2));
        mc1 = fmaxf(mc1, __shfl_xor_sync(0xFFFFFFFF, mc1, 1));
        mc1 = fmaxf(mc1, __shfl_xor_sync(0xFFFFFFFF, mc1, 2));

        float mn0 = fmaxf(mrun0, mc0), mn1 = fmaxf(mrun1, mc1);
        bool chg = (mn0 != mrun0) || (mn1 != mrun1);
        if (__any_sync(0xFFFFFFFF, chg)) {
            float al0 = fexp2(mrun0 - mn0), al1 = fexp2(mrun1 - mn1);
#pragma unroll
            for (int dn = 0; dn < 8; dn++) {
                o[dn][0] *= al0; o[dn][1] *= al0;
                o[dn][2] *= al1; o[dn][3] *= al1;
            }
            l_acc[0] *= al0; l_acc[2] *= al1;
        }
        mrun0 = mn0; mrun1 = mn1;

        // P = 2^(s' - mn) directly in packed fp16
        uint32_t aP[4][4];
#pragma unroll
        for (int jnp = 0; jnp < 4; jnp++) {
            aP[jnp][0] = h2exp2u(packh2(s[2 * jnp][0] - mn0, s[2 * jnp][1] - mn0));
            aP[jnp][1] = h2exp2u(packh2(s[2 * jnp][2] - mn1, s[2 * jnp][3] - mn1));
            aP[jnp][2] = h2exp2u(packh2(s[2 * jnp + 1][0] - mn0, s[2 * jnp + 1][1] - mn0));
            aP[jnp][3] = h2exp2u(packh2(s[2 * jnp + 1][2] - mn1, s[2 * jnp + 1][3] - mn1));
        }

        // row-sum l accumulates as an extra "ones" output column (exact fp32 accum)
#pragma unroll
        for (int kp = 0; kp < 4; kp++)
            mma16816(l_acc, aP[kp], bl);

        // O += P V
#pragma unroll
        for (int kp = 0; kp < 4; kp++)
#pragma unroll
            for (int dnp = 0; dnp < 4; dnp++) {
                uint32_t b[4];
                ldsm_x4_t(b[0], b[1], b[2], b[3], vb + (kp * 16 * FS + dnp * 16) * 2);
                mma16816(o[2 * dnp], aP[kp], b);
                mma16816(o[2 * dnp + 1], aP[kp], b + 2);
            }
    }

    // broadcast row sums within each 4-lane group, normalize, write out
    int src = lane & 28;
    float l0 = __shfl_sync(0xFFFFFFFF, l_acc[0], src);
    float l1 = __shfl_sync(0xFFFFFFFF, l_acc[2], src);
    float inv0 = 1.f / l0, inv1 = 1.f / l1;
    int b = z >> 3, h = z & 7;
    int r0 = m0 + wid * 16 + (lane >> 2);
    __half* outp = g_att + ((size_t)(b * NPIX + r0)) * HID + h * DH + 2 * (lane & 3);
#pragma unroll
    for (int dn = 0; dn < 8; dn++) {
        __half2 v0 = __floats2half2_rn(o[dn][0] * inv0, o[dn][1] * inv0);
        __half2 v1 = __floats2half2_rn(o[dn][2] * inv1, o[dn][3] * inv1);
        *(__half2*)(outp + dn * 8) = v0;
        *(__half2*)(outp + dn * 8 + (size_t)8 * HID) = v1;
    }
}

// ---------------- launcher ----------------
extern "C" void kernel_launch(void* const* d_in, const int* in_sizes, int n_in,
                              void* d_out, int out_size) {
    const float* x      = (const float*)d_in[0];
    const float* gamma  = (const float*)d_in[1];
    const float* mem_kv = (const float*)d_in[2];
    const float* w_qkv  = (const float*)d_in[3];
    const float* w_out  = (const float*)d_in[4];
    float* out = (float*)d_out;

    cudaFuncSetAttribute(gemm_kernel<0>, cudaFuncAttributeMaxDynamicSharedMemorySize, GSMEM);
    cudaFuncSetAttribute(gemm_kernel<3>, cudaFuncAttributeMaxDynamicSharedMemorySize, GSMEM);
    cudaFuncSetAttribute(flash_kernel,   cudaFuncAttributeMaxDynamicSharedMemorySize, FSMEM);
    cudaFuncSetAttribute(norm_fused_kernel, cudaFuncAttributeMaxDynamicSharedMemorySize, NA_SMEM);

    cvt_w_kernel<<<(QKV3 * DIM + DIM * HID) / 256, 256>>>(w_qkv, w_out);
    norm_fused_kernel<<<dim3(NPIX / 32, BATCH), 256, NA_SMEM>>>(x, gamma);
    init_kv_kernel<<<ZBH, 256>>>(mem_kv);

    // GEMM1: qkv projection [16384 x 1536 x 512] -> scatter to q/k/v
    gemm_kernel<0><<<dim3(QKV3 / 128, NTOK / 128), 256, GSMEM>>>(nullptr);
    // fused flash attention: per (z, 128-query tile)
    flash_kernel<<<dim3(NPIX / 128, ZBH), 256, FSMEM>>>();
    // GEMM4: out projection [16384 x 512 x 512] -> transposed fp32 write
    gemm_kernel<3><<<dim3(HID / 128, NTOK / 128), 256, GSMEM>>>(out);
}